// round 6
// baseline (speedup 1.0000x reference)
#include <cuda_runtime.h>

#define DD 1024
#define NN 512
#define RR 513
#define TPB 256
#define KMAX 128
#define CAND_CAP 320

// Twiddle table: g_tw[k] = (cos, -sin)(2*pi*k/1024), k=0..512, double-rounded to float.
__device__ float2 g_tw[RR];

__global__ void tw_init_kernel() {
    int i = blockIdx.x * blockDim.x + threadIdx.x;
    if (i < RR) {
        double a = (double)i / (double)NN;  // angle = 2*pi*i/1024 = pi*a
        g_tw[i] = make_float2((float)cospi(a), (float)(-sinpi(a)));
    }
}

// XLA EmitHypot emulation in strict fp32 RN
__device__ __forceinline__ float xla_hypot(float re, float im) {
    float a = fabsf(re), b = fabsf(im);
    float mx = fmaxf(a, b), mn = fminf(a, b);
    if (mx == 0.f) return 0.f;
    float div = __fdiv_rn(mn, mx);
    float t = __fadd_rn(1.f, __fmul_rn(div, div));
    return __fmul_rn(mx, __fsqrt_rn(t));
}

// ---- ducc/pocketfft radf4, bit-exact fp32 emulation, NO FP CONTRACTION ----
// MULPM with -ffp-contract=off semantics: a = rn(rn(c*e) + rn(d*f));
//                                         b = rn(rn(c*f) - rn(d*e))
__device__ __forceinline__ void radf4_pass(
    const float* __restrict__ cc, float* __restrict__ ch,
    const float2* __restrict__ tw, int ido, int l1, int m_step, int t)
{
    // section 1: i=0, t in [0, l1)
    if (t < l1) {
        int k = t;
        float c0 = cc[ido * k];
        float c1 = cc[ido * (k + l1)];
        float c2 = cc[ido * (k + 2 * l1)];
        float c3 = cc[ido * (k + 3 * l1)];
        float tr1 = c3 + c1;
        float tr2 = c0 + c2;
        ch[ido * (4 * k)]               = tr2 + tr1;
        ch[(ido - 1) + ido * (1 + 4*k)] = c0 - c2;
        ch[ido * (2 + 4 * k)]           = c3 - c1;
        ch[(ido - 1) + ido * (3 + 4*k)] = tr2 - tr1;
    }
    if (ido == 1) return;
    const int nI = (ido >> 1) - 1;
    const int s2 = l1, e2 = l1 + l1 * nI;
    // section 2: complex butterflies with twiddles
    if (t >= s2 && t < e2) {
        int q = t - s2;
        int k = q / nI, ii = q % nI;
        int i = 2 + 2 * ii;
        int ic = ido - i;
        int m1 = (i >> 1) * m_step;
        float2 t1 = tw[m1], t2 = tw[2 * m1], t3 = tw[3 * m1];
        float w1r = t1.x, w1i = -t1.y;
        float w2r = t2.x, w2i = -t2.y;
        float w3r = t3.x, w3i = -t3.y;
        float ccr1 = cc[(i-1) + ido*(k + l1)],     cci1 = cc[i + ido*(k + l1)];
        float ccr2 = cc[(i-1) + ido*(k + 2*l1)],   cci2 = cc[i + ido*(k + 2*l1)];
        float ccr3 = cc[(i-1) + ido*(k + 3*l1)],   cci3 = cc[i + ido*(k + 3*l1)];
        float cr2 = __fadd_rn(__fmul_rn(w1r, ccr1), __fmul_rn(w1i, cci1));
        float ci2 = __fsub_rn(__fmul_rn(w1r, cci1), __fmul_rn(w1i, ccr1));
        float cr3 = __fadd_rn(__fmul_rn(w2r, ccr2), __fmul_rn(w2i, cci2));
        float ci3 = __fsub_rn(__fmul_rn(w2r, cci2), __fmul_rn(w2i, ccr2));
        float cr4 = __fadd_rn(__fmul_rn(w3r, ccr3), __fmul_rn(w3i, cci3));
        float ci4 = __fsub_rn(__fmul_rn(w3r, cci3), __fmul_rn(w3i, ccr3));
        float tr1 = cr4 + cr2, tr4 = cr4 - cr2;
        float ti1 = ci2 + ci4, ti4 = ci2 - ci4;
        float c0r = cc[(i-1) + ido*k], c0i = cc[i + ido*k];
        float tr2 = c0r + cr3, tr3 = c0r - cr3;
        float ti2 = c0i + ci3, ti3 = c0i - ci3;
        ch[(i-1)  + ido*(4*k)]     = tr1 + tr2;
        ch[(ic-1) + ido*(3 + 4*k)] = tr2 - tr1;
        ch[i      + ido*(4*k)]     = ti1 + ti2;
        ch[ic     + ido*(3 + 4*k)] = ti1 - ti2;
        ch[(i-1)  + ido*(2 + 4*k)] = ti4 + tr3;
        ch[(ic-1) + ido*(1 + 4*k)] = tr3 - ti4;
        ch[i      + ido*(2 + 4*k)] = tr4 + ti3;
        ch[ic     + ido*(1 + 4*k)] = tr4 - ti3;
    }
    // section 3: tail i=ido (ido even)
    if (t >= e2 && t < e2 + l1) {
        int k = t - e2;
        const float HS = 0.70710678118654752440f;
        float a  = cc[(ido-1) + ido*(k + l1)];
        float b  = cc[(ido-1) + ido*(k + 3*l1)];
        float cv = cc[(ido-1) + ido*(k + 2*l1)];
        float c0 = cc[(ido-1) + ido*k];
        float ti1 = __fmul_rn(-HS, __fadd_rn(a, b));
        float tr1 = __fmul_rn( HS, __fsub_rn(a, b));
        ch[(ido-1) + ido*(4*k)]     = c0 + tr1;
        ch[(ido-1) + ido*(2 + 4*k)] = c0 - tr1;
        ch[ido*(3 + 4*k)]           = ti1 + cv;
        ch[ido*(1 + 4*k)]           = ti1 - cv;
    }
}

__global__ __launch_bounds__(TPB) void spectral_kernel(
    const float* __restrict__ x, const float* __restrict__ gains,
    const float* __restrict__ bias, float* __restrict__ y, int kk)
{
    __shared__ float4 s_pool[512];                // 8KB: fwd ping-pong / inverse complex
    __shared__ float2 s_tw[RR];
    __shared__ float2 s_X[RR];
    __shared__ unsigned long long s_key[RR];
    __shared__ float  s_mag[RR];
    __shared__ float  s_sc[RR];
    __shared__ float  s_g[KMAX];
    __shared__ int    s_hist[256];
    __shared__ unsigned long long s_ckey[CAND_CAP];
    __shared__ float  s_wmax[8];
    __shared__ int    s_cut;
    __shared__ int    s_cnt;

    float* cbuf = (float*)s_pool;        // [1024]
    float* hbuf = cbuf + 1024;           // [1024]

    const int t = threadIdx.x;
    const long long row = blockIdx.x;
    const float4* xr4 = (const float4*)(x + row * DD);

    for (int i = t; i < RR; i += TPB) s_tw[i] = g_tw[i];
    for (int i = t; i < kk; i += TPB) s_g[i] = gains[i];
    {   // load row natural order
        float4 v = xr4[t];
        cbuf[4*t] = v.x; cbuf[4*t+1] = v.y; cbuf[4*t+2] = v.z; cbuf[4*t+3] = v.w;
    }
    if (t == 0) s_cnt = 0;
    __syncthreads();

    // ---- forward rfft: ducc radf4 x5, bit-exact fp32 (no contraction) ----
    radf4_pass(cbuf, hbuf, s_tw,   1, 256, 256, t); __syncthreads();
    radf4_pass(hbuf, cbuf, s_tw,   4,  64,  64, t); __syncthreads();
    radf4_pass(cbuf, hbuf, s_tw,  16,  16,  16, t); __syncthreads();
    radf4_pass(hbuf, cbuf, s_tw,  64,   4,   4, t); __syncthreads();
    radf4_pass(cbuf, hbuf, s_tw, 256,   1,   1, t); __syncthreads();
    // hbuf = halfcomplex: [X0, X1r, X1i, X2r, X2i, ..., X511r, X511i, X512]

    // ---- unpack bins, magnitudes (XLA EmitHypot), keys ----
    {
#pragma unroll
        for (int h = 0; h < 2; ++h) {
            int k = t + h * 256;
            float xrf, xif;
            if (k == 0) { xrf = hbuf[0]; xif = 0.f; }
            else        { xrf = hbuf[2*k - 1]; xif = hbuf[2*k]; }
            float mag = xla_hypot(xrf, xif);
            s_key[k] = (((unsigned long long)__float_as_uint(mag)) << 10)
                     | (unsigned long long)(1023 - k);
            s_mag[k] = mag;
            s_X[k]   = make_float2(xrf, xif);
            s_sc[k]  = 0.f;
        }
        if (t == 0) {
            float xrf = hbuf[1023], xif = 0.f;
            float mag = xla_hypot(xrf, xif);
            s_key[512] = (((unsigned long long)__float_as_uint(mag)) << 10)
                       | (unsigned long long)(1023 - 512);
            s_mag[512] = mag;
            s_X[512]   = make_float2(xrf, xif);
            s_sc[512]  = 0.f;
        }
    }
    __syncthreads();

    // ---- max mag (block reduce) ----
    float mv = fmaxf(s_mag[t], s_mag[t + 256]);
    if (t == 0) mv = fmaxf(mv, s_mag[512]);
#pragma unroll
    for (int o = 16; o; o >>= 1) mv = fmaxf(mv, __shfl_xor_sync(0xffffffffu, mv, o));
    if ((t & 31) == 0) s_wmax[t >> 5] = mv;
    __syncthreads();
    if (t == 0) {
        float m2 = s_wmax[0];
#pragma unroll
        for (int i2 = 1; i2 < 8; ++i2) m2 = fmaxf(m2, s_wmax[i2]);
        s_wmax[0] = m2 * 1.0000002f + 1e-30f;
    }
    __syncthreads();

    // ---- histogram radix-select for the kk-th largest mag ----
    float lo = 0.f, hi = s_wmax[0];
    int base = 0, cutb = 0, ccnt = 0;
    float inv = 0.f;
    for (int it = 0; it < 4; ++it) {
        __syncthreads();
        inv = 256.f / (hi - lo);
        s_hist[t] = 0;
        __syncthreads();
        for (int f = t; f < RR; f += TPB) {
            float m = s_mag[f];
            if (m >= lo && m < hi) {
                int b = (int)((m - lo) * inv);
                b = min(b, 255);
                atomicAdd(&s_hist[b], 1);
            }
        }
        __syncthreads();
#pragma unroll
        for (int d = 1; d < 256; d <<= 1) {
            int v = s_hist[t] + ((t + d < 256) ? s_hist[t + d] : 0);
            __syncthreads();
            s_hist[t] = v;
            __syncthreads();
        }
        {
            int sa = base + s_hist[t];
            int sb = (t == 255) ? base : (base + s_hist[t + 1]);
            if (sa >= kk && sb < kk) s_cut = t;
        }
        __syncthreads();
        cutb = s_cut;
        ccnt = base + s_hist[cutb];
        if (ccnt <= 256) break;
        int nbase = base + ((cutb < 255) ? s_hist[cutb + 1] : 0);
        float wbin = (hi - lo) * (1.f / 256.f);
        float nlo = lo + cutb * wbin;
        float nhi = lo + (cutb + 1) * wbin;
        base = nbase; lo = nlo; hi = nhi;
    }
    __syncthreads();

    // ---- compact candidates ----
    for (int f = t; f < RR; f += TPB) {
        float m = s_mag[f];
        bool cand;
        if (m >= hi) cand = true;
        else if (m >= lo) {
            int b = (int)((m - lo) * inv);
            b = min(b, 255);
            cand = (b >= cutb);
        } else cand = false;
        if (cand) {
            int pos = atomicAdd(&s_cnt, 1);
            if (pos < CAND_CAP) s_ckey[pos] = s_key[f];
        }
    }
    __syncthreads();

    // ---- exact rank by pairwise counting; scatter gains by rank ----
    {
        int cnt = min(s_cnt, CAND_CAP);
        for (int i = t; i < cnt; i += TPB) {
            unsigned long long ki = s_ckey[i];
            int r = 0;
            for (int j = 0; j < cnt; ++j) r += (s_ckey[j] > ki) ? 1 : 0;
            if (r < kk) {
                int f = 1023 - (int)(ki & 1023ull);
                s_sc[f] = s_g[r];
            }
        }
    }
    __syncthreads();

    // ---- pack scaled Hermitian spectrum for inverse (fp32, store bit-reversed) ----
    float2* zb = (float2*)s_pool;   // reuse pool as complex[512]
    {
        const float sc1 = 1.f / 1024.f;   // 0.5 (pack) * 1/512 (ifft norm)
        float2 st[2];
#pragma unroll
        for (int h = 0; h < 2; ++h) {
            int k  = t + h * 256;        // 0..511
            int km = NN - k;             // pair index, uses X[512] at k=0
            float2 Yk = s_X[k];  float a1 = s_sc[k];  Yk.x *= a1; Yk.y *= a1;
            float2 Ym = s_X[km]; float a2 = s_sc[km]; Ym.x *= a2; Ym.y *= a2;
            float px = Yk.x + Ym.x, py = Yk.y - Ym.y;
            float qx = Yk.x - Ym.x, qy = Yk.y + Ym.y;
            float2 w = s_tw[k];          // conj(w) = exp(+2pi i k/1024)
            float tx = qx * w.x + qy * w.y;
            float ty = qy * w.x - qx * w.y;
            st[h] = make_float2(sc1 * (px - ty), sc1 * (py + tx));
        }
        __syncthreads();    // all reads of s_X/hbuf done before pool overwrite
#pragma unroll
        for (int h = 0; h < 2; ++h) {
            int k = t + h * 256;
            zb[__brev(k) >> 23] = st[h];
        }
    }
    __syncthreads();

    // ---- inverse 512-pt FFT (fp32), DIT radix-2 (bitrev in -> natural out) ----
#pragma unroll
    for (int ls = 1; ls <= 9; ++ls) {
        const int half = 1 << (ls - 1);
        const int j = t & (half - 1);
        const int i0 = (t << 1) - j;
        float2 u  = zb[i0];
        float2 vv = zb[i0 + half];
        float2 w  = s_tw[j << (10 - ls)];
        float vx = vv.x * w.x + vv.y * w.y;   // v * conj(w)
        float vy = vv.y * w.x - vv.x * w.y;
        zb[i0]        = make_float2(u.x + vx, u.y + vy);
        zb[i0 + half] = make_float2(u.x - vx, u.y - vy);
        __syncthreads();
    }

    // ---- write y = irfft + bias ----
    {
        const float2* b2 = (const float2*)bias;
        float2* yr = (float2*)(y + row * DD);
#pragma unroll
        for (int h = 0; h < 2; ++h) {
            int n = t + h * 256;
            float2 z  = zb[n];
            float2 bb = b2[n];
            yr[n] = make_float2(z.x + bb.x, z.y + bb.y);
        }
    }
}

extern "C" void kernel_launch(void* const* d_in, const int* in_sizes, int n_in,
                              void* d_out, int out_size) {
    const float* x     = (const float*)d_in[0];
    const float* gains = (const float*)d_in[1];
    const float* bias  = (const float*)d_in[2];
    float* y = (float*)d_out;

    int rows = in_sizes[0] / DD;
    int kk = in_sizes[1];
    if (kk > KMAX) kk = KMAX;

    tw_init_kernel<<<3, 256>>>();
    spectral_kernel<<<rows, TPB>>>(x, gains, bias, y, kk);
}

// round 7
// speedup vs baseline: 1.1995x; 1.1995x over previous
#include <cuda_runtime.h>

#define DD 1024
#define NN 512
#define RR 513
#define TPB 256
#define KMAX 128
#define CAND_CAP 320

// padded index for inverse-FFT smem buffer (float2 units): 8B pad every 16
#define PIDX(i) ((i) + ((i) >> 4))

// Twiddle table: g_tw[k] = (cos, -sin)(2*pi*k/1024), k=0..512, double-rounded to float.
__device__ float2 g_tw[RR];

__global__ void tw_init_kernel() {
    int i = blockIdx.x * blockDim.x + threadIdx.x;
    if (i < RR) {
        double a = (double)i / (double)NN;
        g_tw[i] = make_float2((float)cospi(a), (float)(-sinpi(a)));
    }
}

// XLA EmitHypot emulation in strict fp32 RN
__device__ __forceinline__ float xla_hypot(float re, float im) {
    float a = fabsf(re), b = fabsf(im);
    float mx = fmaxf(a, b), mn = fminf(a, b);
    if (mx == 0.f) return 0.f;
    float div = __fdiv_rn(mn, mx);
    float t = __fadd_rn(1.f, __fmul_rn(div, div));
    return __fmul_rn(mx, __fsqrt_rn(t));
}

// z * conj(w)  (free-form fp32; inverse path is not bit-constrained)
__device__ __forceinline__ float2 cmulc(float2 z, float2 w) {
    return make_float2(fmaf(z.x, w.x,  z.y * w.y),
                       fmaf(z.y, w.x, -z.x * w.y));
}

// ---- ducc/pocketfft radf4, bit-exact fp32 emulation, NO FP CONTRACTION ----
// Arithmetic DAG identical to R6-passing version; only memory layout/vectorization
// differs (osh shifts the output array by 1 float; pass ido==1 uses a float4 store).
__device__ __forceinline__ void radf4_pass(
    const float* __restrict__ cc, float* __restrict__ ch,
    const float2* __restrict__ tw, int ido, int l1, int m_step, int t, int osh)
{
    if (ido == 1) {
        if (t < l1) {
            int k = t;
            float c0 = cc[k];
            float c1 = cc[k + l1];
            float c2 = cc[k + 2 * l1];
            float c3 = cc[k + 3 * l1];
            float tr1 = c3 + c1;
            float tr2 = c0 + c2;
            // contiguous halfcomplex quad -> single STS.128
            ((float4*)ch)[k] = make_float4(tr2 + tr1, c0 - c2, c3 - c1, tr2 - tr1);
        }
        return;
    }
    // section 1: i=0
    if (t < l1) {
        int k = t;
        float c0 = cc[ido * k];
        float c1 = cc[ido * (k + l1)];
        float c2 = cc[ido * (k + 2 * l1)];
        float c3 = cc[ido * (k + 3 * l1)];
        float tr1 = c3 + c1;
        float tr2 = c0 + c2;
        ch[osh + ido * (4 * k)]               = tr2 + tr1;
        ch[osh + (ido - 1) + ido * (1 + 4*k)] = c0 - c2;
        ch[osh + ido * (2 + 4 * k)]           = c3 - c1;
        ch[osh + (ido - 1) + ido * (3 + 4*k)] = tr2 - tr1;
    }
    const int nI = (ido >> 1) - 1;
    const int s2 = l1, e2 = l1 + l1 * nI;
    // section 2: complex butterflies with twiddles
    if (t >= s2 && t < e2) {
        int q = t - s2;
        int k = q / nI, ii = q % nI;
        int i = 2 + 2 * ii;
        int ic = ido - i;
        int m1 = (i >> 1) * m_step;
        float2 t1 = tw[m1], t2 = tw[2 * m1], t3 = tw[3 * m1];
        float w1r = t1.x, w1i = -t1.y;
        float w2r = t2.x, w2i = -t2.y;
        float w3r = t3.x, w3i = -t3.y;
        float ccr1 = cc[(i-1) + ido*(k + l1)],     cci1 = cc[i + ido*(k + l1)];
        float ccr2 = cc[(i-1) + ido*(k + 2*l1)],   cci2 = cc[i + ido*(k + 2*l1)];
        float ccr3 = cc[(i-1) + ido*(k + 3*l1)],   cci3 = cc[i + ido*(k + 3*l1)];
        float cr2 = __fadd_rn(__fmul_rn(w1r, ccr1), __fmul_rn(w1i, cci1));
        float ci2 = __fsub_rn(__fmul_rn(w1r, cci1), __fmul_rn(w1i, ccr1));
        float cr3 = __fadd_rn(__fmul_rn(w2r, ccr2), __fmul_rn(w2i, cci2));
        float ci3 = __fsub_rn(__fmul_rn(w2r, cci2), __fmul_rn(w2i, ccr2));
        float cr4 = __fadd_rn(__fmul_rn(w3r, ccr3), __fmul_rn(w3i, cci3));
        float ci4 = __fsub_rn(__fmul_rn(w3r, cci3), __fmul_rn(w3i, ccr3));
        float tr1 = cr4 + cr2, tr4 = cr4 - cr2;
        float ti1 = ci2 + ci4, ti4 = ci2 - ci4;
        float c0r = cc[(i-1) + ido*k], c0i = cc[i + ido*k];
        float tr2 = c0r + cr3, tr3 = c0r - cr3;
        float ti2 = c0i + ci3, ti3 = c0i - ci3;
        ch[osh + (i-1)  + ido*(4*k)]     = tr1 + tr2;
        ch[osh + (ic-1) + ido*(3 + 4*k)] = tr2 - tr1;
        ch[osh + i      + ido*(4*k)]     = ti1 + ti2;
        ch[osh + ic     + ido*(3 + 4*k)] = ti1 - ti2;
        ch[osh + (i-1)  + ido*(2 + 4*k)] = ti4 + tr3;
        ch[osh + (ic-1) + ido*(1 + 4*k)] = tr3 - ti4;
        ch[osh + i      + ido*(2 + 4*k)] = tr4 + ti3;
        ch[osh + ic     + ido*(1 + 4*k)] = tr4 - ti3;
    }
    // section 3: tail i=ido
    if (t >= e2 && t < e2 + l1) {
        int k = t - e2;
        const float HS = 0.70710678118654752440f;
        float a  = cc[(ido-1) + ido*(k + l1)];
        float b  = cc[(ido-1) + ido*(k + 3*l1)];
        float cv = cc[(ido-1) + ido*(k + 2*l1)];
        float c0 = cc[(ido-1) + ido*k];
        float ti1 = __fmul_rn(-HS, __fadd_rn(a, b));
        float tr1 = __fmul_rn( HS, __fsub_rn(a, b));
        ch[osh + (ido-1) + ido*(4*k)]     = c0 + tr1;
        ch[osh + (ido-1) + ido*(2 + 4*k)] = c0 - tr1;
        ch[osh + ido*(3 + 4*k)]           = ti1 + cv;
        ch[osh + ido*(1 + 4*k)]           = ti1 - cv;
    }
}

__global__ __launch_bounds__(TPB) void spectral_kernel(
    const float* __restrict__ x, const float* __restrict__ gains,
    const float* __restrict__ bias, float* __restrict__ y, int kk)
{
    __shared__ float4 s_pool[520];                // 2080 floats: cbuf[1024] + hbuf[1025+]
    __shared__ float2 s_tw[RR];
    __shared__ float2 s_X[RR];
    __shared__ unsigned long long s_key[RR];
    __shared__ float  s_mag[RR];
    __shared__ float  s_sc[RR];
    __shared__ float  s_g[KMAX];
    __shared__ int    s_hist[256];
    __shared__ unsigned long long s_ckey[CAND_CAP];
    __shared__ float  s_wmax[8];
    __shared__ int    s_cut;
    __shared__ int    s_cnt;

    float* cbuf = (float*)s_pool;        // [0..1023]
    float* hbuf = cbuf + 1024;           // [1024..2048] (pass5 writes osh=1 -> up to hbuf[1024])

    const int t = threadIdx.x;
    const long long row = blockIdx.x;
    const float4* xr4 = (const float4*)(x + row * DD);

    for (int i = t; i < RR; i += TPB) s_tw[i] = g_tw[i];
    for (int i = t; i < kk; i += TPB) s_g[i] = gains[i];
    ((float4*)cbuf)[t] = xr4[t];
    if (t == 0) s_cnt = 0;
    __syncthreads();

    // ---- forward rfft: ducc radf4 x5, bit-exact fp32 (no contraction) ----
    radf4_pass(cbuf, hbuf, s_tw,   1, 256, 256, t, 0); __syncthreads();
    radf4_pass(hbuf, cbuf, s_tw,   4,  64,  64, t, 0); __syncthreads();
    radf4_pass(cbuf, hbuf, s_tw,  16,  16,  16, t, 0); __syncthreads();
    radf4_pass(hbuf, cbuf, s_tw,  64,   4,   4, t, 0); __syncthreads();
    radf4_pass(cbuf, hbuf, s_tw, 256,   1,   1, t, 1); __syncthreads();
    // hbuf (shift 1): X0 = hbuf[1]; Xk = (hbuf[2k], hbuf[2k+1]) k=1..511; X512 = hbuf[1024]

    // ---- unpack bins, magnitudes (XLA EmitHypot), keys ----
    {
        const float2* h2 = (const float2*)hbuf;   // aligned pairs (hbuf[2k], hbuf[2k+1])
#pragma unroll
        for (int h = 0; h < 2; ++h) {
            int k = t + h * 256;
            float xrf, xif;
            if (k == 0) { xrf = hbuf[1]; xif = 0.f; }
            else        { float2 v = h2[k]; xrf = v.x; xif = v.y; }
            float mag = xla_hypot(xrf, xif);
            s_key[k] = (((unsigned long long)__float_as_uint(mag)) << 10)
                     | (unsigned long long)(1023 - k);
            s_mag[k] = mag;
            s_X[k]   = make_float2(xrf, xif);
            s_sc[k]  = 0.f;
        }
        if (t == 0) {
            float xrf = hbuf[1024], xif = 0.f;
            float mag = xla_hypot(xrf, xif);
            s_key[512] = (((unsigned long long)__float_as_uint(mag)) << 10)
                       | (unsigned long long)(1023 - 512);
            s_mag[512] = mag;
            s_X[512]   = make_float2(xrf, xif);
            s_sc[512]  = 0.f;
        }
    }
    __syncthreads();

    // ---- max mag (block reduce) ----
    float mv = fmaxf(s_mag[t], s_mag[t + 256]);
    if (t == 0) mv = fmaxf(mv, s_mag[512]);
#pragma unroll
    for (int o = 16; o; o >>= 1) mv = fmaxf(mv, __shfl_xor_sync(0xffffffffu, mv, o));
    if ((t & 31) == 0) s_wmax[t >> 5] = mv;
    __syncthreads();
    if (t == 0) {
        float m2 = s_wmax[0];
#pragma unroll
        for (int i2 = 1; i2 < 8; ++i2) m2 = fmaxf(m2, s_wmax[i2]);
        s_wmax[0] = m2 * 1.0000002f + 1e-30f;
    }
    __syncthreads();

    // ---- histogram radix-select for the kk-th largest mag ----
    float lo = 0.f, hi = s_wmax[0];
    int base = 0, cutb = 0, ccnt = 0;
    float inv = 0.f;
    for (int it = 0; it < 4; ++it) {
        __syncthreads();
        inv = 256.f / (hi - lo);
        s_hist[t] = 0;
        __syncthreads();
        for (int f = t; f < RR; f += TPB) {
            float m = s_mag[f];
            if (m >= lo && m < hi) {
                int b = (int)((m - lo) * inv);
                b = min(b, 255);
                atomicAdd(&s_hist[b], 1);
            }
        }
        __syncthreads();
#pragma unroll
        for (int d = 1; d < 256; d <<= 1) {
            int v = s_hist[t] + ((t + d < 256) ? s_hist[t + d] : 0);
            __syncthreads();
            s_hist[t] = v;
            __syncthreads();
        }
        {
            int sa = base + s_hist[t];
            int sb = (t == 255) ? base : (base + s_hist[t + 1]);
            if (sa >= kk && sb < kk) s_cut = t;
        }
        __syncthreads();
        cutb = s_cut;
        ccnt = base + s_hist[cutb];
        if (ccnt <= 256) break;
        int nbase = base + ((cutb < 255) ? s_hist[cutb + 1] : 0);
        float wbin = (hi - lo) * (1.f / 256.f);
        float nlo = lo + cutb * wbin;
        float nhi = lo + (cutb + 1) * wbin;
        base = nbase; lo = nlo; hi = nhi;
    }
    __syncthreads();

    // ---- compact candidates ----
    for (int f = t; f < RR; f += TPB) {
        float m = s_mag[f];
        bool cand;
        if (m >= hi) cand = true;
        else if (m >= lo) {
            int b = (int)((m - lo) * inv);
            b = min(b, 255);
            cand = (b >= cutb);
        } else cand = false;
        if (cand) {
            int pos = atomicAdd(&s_cnt, 1);
            if (pos < CAND_CAP) s_ckey[pos] = s_key[f];
        }
    }
    __syncthreads();

    // ---- exact rank by pairwise counting; scatter gains by rank ----
    {
        int cnt = min(s_cnt, CAND_CAP);
        for (int i = t; i < cnt; i += TPB) {
            unsigned long long ki = s_ckey[i];
            int r = 0;
            for (int j = 0; j < cnt; ++j) r += (s_ckey[j] > ki) ? 1 : 0;
            if (r < kk) {
                int f = 1023 - (int)(ki & 1023ull);
                s_sc[f] = s_g[r];
            }
        }
    }
    __syncthreads();

    // ---- pack scaled Hermitian spectrum for inverse (bitrev scatter, padded) ----
    float2* zb = (float2*)s_pool;   // padded complex buffer, PIDX indexing
    {
        const float sc1 = 1.f / 1024.f;
#pragma unroll
        for (int h = 0; h < 2; ++h) {
            int k  = t + h * 256;        // 0..511
            int km = NN - k;             // uses X[512] at k=0
            float2 Yk = s_X[k];  float a1 = s_sc[k];  Yk.x *= a1; Yk.y *= a1;
            float2 Ym = s_X[km]; float a2 = s_sc[km]; Ym.x *= a2; Ym.y *= a2;
            float px = Yk.x + Ym.x, py = Yk.y - Ym.y;
            float qx = Yk.x - Ym.x, qy = Yk.y + Ym.y;
            float2 w = s_tw[k];
            float tx = qx * w.x + qy * w.y;
            float ty = qy * w.x - qx * w.y;
            zb[PIDX(__brev(k) >> 23)] = make_float2(sc1 * (px - ty), sc1 * (py + tx));
        }
    }
    __syncthreads();

    // ---- inverse 512-pt FFT: fused double radix-2 stages (1,2)(3,4)(5,6)(7,8) ----
#pragma unroll
    for (int lsp = 1; lsp <= 7; lsp += 2) {
        if (t < 128) {
            const int h1 = 1 << (lsp - 1);
            const int low = t & (h1 - 1);
            const int high = t >> (lsp - 1);
            const int bidx = low | (high << (lsp + 1));
            float2 z0 = zb[PIDX(bidx)];
            float2 z1 = zb[PIDX(bidx + h1)];
            float2 z2 = zb[PIDX(bidx + 2 * h1)];
            float2 z3 = zb[PIDX(bidx + 3 * h1)];
            float2 wa = s_tw[low << (10 - lsp)];
            int wbi = low << (9 - lsp);
            float2 wb = s_tw[wbi];
            float2 wc = s_tw[wbi + 256];
            // stage lsp
            float2 t1 = cmulc(z1, wa);
            float2 a0 = make_float2(z0.x + t1.x, z0.y + t1.y);
            float2 a1 = make_float2(z0.x - t1.x, z0.y - t1.y);
            float2 t2 = cmulc(z3, wa);
            float2 a2 = make_float2(z2.x + t2.x, z2.y + t2.y);
            float2 a3 = make_float2(z2.x - t2.x, z2.y - t2.y);
            // stage lsp+1
            float2 u = cmulc(a2, wb);
            float2 v = cmulc(a3, wc);
            zb[PIDX(bidx)]          = make_float2(a0.x + u.x, a0.y + u.y);
            zb[PIDX(bidx + h1)]     = make_float2(a1.x + v.x, a1.y + v.y);
            zb[PIDX(bidx + 2*h1)]   = make_float2(a0.x - u.x, a0.y - u.y);
            zb[PIDX(bidx + 3*h1)]   = make_float2(a1.x - v.x, a1.y - v.y);
        }
        __syncthreads();
    }

    // ---- final stage (ls=9) in registers, fused with bias add + gmem write ----
    {
        const float2* b2 = (const float2*)bias;
        float2* yr = (float2*)(y + row * DD);
        float2 u = zb[PIDX(t)];
        float2 v = zb[PIDX(t + 256)];
        float2 w = s_tw[t << 1];
        float2 vp = cmulc(v, w);
        float2 bb0 = b2[t];
        float2 bb1 = b2[t + 256];
        yr[t]       = make_float2(u.x + vp.x + bb0.x, u.y + vp.y + bb0.y);
        yr[t + 256] = make_float2(u.x - vp.x + bb1.x, u.y - vp.y + bb1.y);
    }
}

extern "C" void kernel_launch(void* const* d_in, const int* in_sizes, int n_in,
                              void* d_out, int out_size) {
    const float* x     = (const float*)d_in[0];
    const float* gains = (const float*)d_in[1];
    const float* bias  = (const float*)d_in[2];
    float* y = (float*)d_out;

    int rows = in_sizes[0] / DD;
    int kk = in_sizes[1];
    if (kk > KMAX) kk = KMAX;

    tw_init_kernel<<<3, 256>>>();
    spectral_kernel<<<rows, TPB>>>(x, gains, bias, y, kk);
}

// round 8
// speedup vs baseline: 1.4667x; 1.2227x over previous
#include <cuda_runtime.h>

#define DD 1024
#define NN 512
#define RR 513
#define TPB 256
#define KMAX 128
#define CKMAX 513

// padded index for inverse-FFT smem buffer (float2 units): 8B pad every 16
#define PIDX(i) ((i) + ((i) >> 4))

// Twiddle table: g_tw[k] = (cos, -sin)(2*pi*k/1024), k=0..512, double-rounded to float.
__device__ float2 g_tw[RR];

__global__ void tw_init_kernel() {
    int i = blockIdx.x * blockDim.x + threadIdx.x;
    if (i < RR) {
        double a = (double)i / (double)NN;
        g_tw[i] = make_float2((float)cospi(a), (float)(-sinpi(a)));
    }
}

// XLA EmitHypot emulation in strict fp32 RN
__device__ __forceinline__ float xla_hypot(float re, float im) {
    float a = fabsf(re), b = fabsf(im);
    float mx = fmaxf(a, b), mn = fminf(a, b);
    if (mx == 0.f) return 0.f;
    float div = __fdiv_rn(mn, mx);
    float t = __fadd_rn(1.f, __fmul_rn(div, div));
    return __fmul_rn(mx, __fsqrt_rn(t));
}

// z * conj(w)  (free-form fp32; inverse path is not bit-constrained)
__device__ __forceinline__ float2 cmulc(float2 z, float2 w) {
    return make_float2(fmaf(z.x, w.x,  z.y * w.y),
                       fmaf(z.y, w.x, -z.x * w.y));
}

// ---- ducc/pocketfft radf4, bit-exact fp32 emulation, NO FP CONTRACTION ----
__device__ __forceinline__ void radf4_pass(
    const float* __restrict__ cc, float* __restrict__ ch,
    const float2* __restrict__ tw, int ido, int l1, int m_step, int t, int osh)
{
    if (ido == 1) {
        if (t < l1) {
            int k = t;
            float c0 = cc[k];
            float c1 = cc[k + l1];
            float c2 = cc[k + 2 * l1];
            float c3 = cc[k + 3 * l1];
            float tr1 = c3 + c1;
            float tr2 = c0 + c2;
            ((float4*)ch)[k] = make_float4(tr2 + tr1, c0 - c2, c3 - c1, tr2 - tr1);
        }
        return;
    }
    // section 1: i=0
    if (t < l1) {
        int k = t;
        float c0 = cc[ido * k];
        float c1 = cc[ido * (k + l1)];
        float c2 = cc[ido * (k + 2 * l1)];
        float c3 = cc[ido * (k + 3 * l1)];
        float tr1 = c3 + c1;
        float tr2 = c0 + c2;
        ch[osh + ido * (4 * k)]               = tr2 + tr1;
        ch[osh + (ido - 1) + ido * (1 + 4*k)] = c0 - c2;
        ch[osh + ido * (2 + 4 * k)]           = c3 - c1;
        ch[osh + (ido - 1) + ido * (3 + 4*k)] = tr2 - tr1;
    }
    const int nI = (ido >> 1) - 1;
    const int s2 = l1, e2 = l1 + l1 * nI;
    // section 2: complex butterflies with twiddles
    if (t >= s2 && t < e2) {
        int q = t - s2;
        int k = q / nI, ii = q % nI;
        int i = 2 + 2 * ii;
        int ic = ido - i;
        int m1 = (i >> 1) * m_step;
        float2 t1 = tw[m1], t2 = tw[2 * m1], t3 = tw[3 * m1];
        float w1r = t1.x, w1i = -t1.y;
        float w2r = t2.x, w2i = -t2.y;
        float w3r = t3.x, w3i = -t3.y;
        float ccr1 = cc[(i-1) + ido*(k + l1)],     cci1 = cc[i + ido*(k + l1)];
        float ccr2 = cc[(i-1) + ido*(k + 2*l1)],   cci2 = cc[i + ido*(k + 2*l1)];
        float ccr3 = cc[(i-1) + ido*(k + 3*l1)],   cci3 = cc[i + ido*(k + 3*l1)];
        float cr2 = __fadd_rn(__fmul_rn(w1r, ccr1), __fmul_rn(w1i, cci1));
        float ci2 = __fsub_rn(__fmul_rn(w1r, cci1), __fmul_rn(w1i, ccr1));
        float cr3 = __fadd_rn(__fmul_rn(w2r, ccr2), __fmul_rn(w2i, cci2));
        float ci3 = __fsub_rn(__fmul_rn(w2r, cci2), __fmul_rn(w2i, ccr2));
        float cr4 = __fadd_rn(__fmul_rn(w3r, ccr3), __fmul_rn(w3i, cci3));
        float ci4 = __fsub_rn(__fmul_rn(w3r, cci3), __fmul_rn(w3i, ccr3));
        float tr1 = cr4 + cr2, tr4 = cr4 - cr2;
        float ti1 = ci2 + ci4, ti4 = ci2 - ci4;
        float c0r = cc[(i-1) + ido*k], c0i = cc[i + ido*k];
        float tr2 = c0r + cr3, tr3 = c0r - cr3;
        float ti2 = c0i + ci3, ti3 = c0i - ci3;
        ch[osh + (i-1)  + ido*(4*k)]     = tr1 + tr2;
        ch[osh + (ic-1) + ido*(3 + 4*k)] = tr2 - tr1;
        ch[osh + i      + ido*(4*k)]     = ti1 + ti2;
        ch[osh + ic     + ido*(3 + 4*k)] = ti1 - ti2;
        ch[osh + (i-1)  + ido*(2 + 4*k)] = ti4 + tr3;
        ch[osh + (ic-1) + ido*(1 + 4*k)] = tr3 - ti4;
        ch[osh + i      + ido*(2 + 4*k)] = tr4 + ti3;
        ch[osh + ic     + ido*(1 + 4*k)] = tr4 - ti3;
    }
    // section 3: tail i=ido
    if (t >= e2 && t < e2 + l1) {
        int k = t - e2;
        const float HS = 0.70710678118654752440f;
        float a  = cc[(ido-1) + ido*(k + l1)];
        float b  = cc[(ido-1) + ido*(k + 3*l1)];
        float cv = cc[(ido-1) + ido*(k + 2*l1)];
        float c0 = cc[(ido-1) + ido*k];
        float ti1 = __fmul_rn(-HS, __fadd_rn(a, b));
        float tr1 = __fmul_rn( HS, __fsub_rn(a, b));
        ch[osh + (ido-1) + ido*(4*k)]     = c0 + tr1;
        ch[osh + (ido-1) + ido*(2 + 4*k)] = c0 - tr1;
        ch[osh + ido*(3 + 4*k)]           = ti1 + cv;
        ch[osh + ido*(1 + 4*k)]           = ti1 - cv;
    }
}

__global__ __launch_bounds__(TPB) void spectral_kernel(
    const float* __restrict__ x, const float* __restrict__ gains,
    const float* __restrict__ bias, float* __restrict__ y, int kk)
{
    __shared__ float4 s_pool[520];                // 2080 floats
    __shared__ float2 s_tw[RR];
    __shared__ float  s_mag[RR];
    __shared__ float  s_sc[RR];
    __shared__ float  s_g[KMAX];
    __shared__ int    s_hist[256];                // histogram -> suffix counts
    __shared__ int    s_goff[256];                // per-bin placement counters
    __shared__ unsigned long long s_ckey[CKMAX];
    __shared__ unsigned char s_cbin[CKMAX];
    __shared__ int    s_wsumi[8];
    __shared__ float  s_wmax[8];
    __shared__ int    s_cut;

    float* cbuf = (float*)s_pool;        // [0..1023]
    float* hbuf = cbuf + 1024;           // [1024..2048]

    const int t = threadIdx.x;
    const int lane = t & 31;
    const int wrp = t >> 5;
    const long long row = blockIdx.x;
    const float4* xr4 = (const float4*)(x + row * DD);

    for (int i = t; i < RR; i += TPB) s_tw[i] = g_tw[i];
    for (int i = t; i < kk; i += TPB) s_g[i] = gains[i];
    ((float4*)cbuf)[t] = xr4[t];
    __syncthreads();

    // ---- forward rfft: ducc radf4 x5, bit-exact fp32 (no contraction) ----
    radf4_pass(cbuf, hbuf, s_tw,   1, 256, 256, t, 0); __syncthreads();
    radf4_pass(hbuf, cbuf, s_tw,   4,  64,  64, t, 0); __syncthreads();
    radf4_pass(cbuf, hbuf, s_tw,  16,  16,  16, t, 0); __syncthreads();
    radf4_pass(hbuf, cbuf, s_tw,  64,   4,   4, t, 0); __syncthreads();
    radf4_pass(cbuf, hbuf, s_tw, 256,   1,   1, t, 1); __syncthreads();
    // hbuf (shift 1): X0 = hbuf[1]; Xk = (hbuf[2k], hbuf[2k+1]) k=1..511; X512 = hbuf[1024]

    // ---- magnitudes (XLA EmitHypot) ----
    {
        const float2* h2 = (const float2*)hbuf;
#pragma unroll
        for (int h = 0; h < 2; ++h) {
            int k = t + h * 256;
            float xrf, xif;
            if (k == 0) { xrf = hbuf[1]; xif = 0.f; }
            else        { float2 v = h2[k]; xrf = v.x; xif = v.y; }
            s_mag[k] = xla_hypot(xrf, xif);
            s_sc[k]  = 0.f;
        }
        if (t == 0) {
            s_mag[512] = xla_hypot(hbuf[1024], 0.f);
            s_sc[512]  = 0.f;
        }
        s_hist[t] = 0;
        s_goff[t] = 0;
    }
    __syncthreads();

    // ---- max mag (block reduce) ----
    float mv = fmaxf(s_mag[t], s_mag[t + 256]);
    if (t == 0) mv = fmaxf(mv, s_mag[512]);
#pragma unroll
    for (int o = 16; o; o >>= 1) mv = fmaxf(mv, __shfl_xor_sync(0xffffffffu, mv, o));
    if (lane == 0) s_wmax[wrp] = mv;
    __syncthreads();
    if (t == 0) {
        float m2 = s_wmax[0];
#pragma unroll
        for (int i2 = 1; i2 < 8; ++i2) m2 = fmaxf(m2, s_wmax[i2]);
        s_wmax[0] = m2 * 1.0000002f + 1e-30f;
    }
    __syncthreads();

    const float hi = s_wmax[0];
    const float inv = 256.f / hi;

    // ---- single-pass histogram over [0, hi) ----
    for (int f = t; f < RR; f += TPB) {
        int b = min((int)(s_mag[f] * inv), 255);
        atomicAdd(&s_hist[b], 1);
    }
    __syncthreads();

    // ---- suffix scan (warp shuffles): s_hist[b] := count of elements in bins >= b ----
    {
        int v = s_hist[t];
#pragma unroll
        for (int d = 1; d < 32; d <<= 1) {
            int tmp = __shfl_down_sync(0xffffffffu, v, d);
            if (lane + d < 32) v += tmp;
        }
        if (lane == 0) s_wsumi[wrp] = v;
        __syncthreads();
        int add = 0;
#pragma unroll
        for (int w = 0; w < 8; ++w) add += (w > wrp) ? s_wsumi[w] : 0;
        v += add;
        s_hist[t] = v;
    }
    __syncthreads();

    // ---- cut bin: s_hist[cut] >= kk, s_hist[cut+1] < kk ----
    {
        int sa = s_hist[t];
        int sb = (t == 255) ? 0 : s_hist[t + 1];
        if (sa >= kk && sb < kk) s_cut = t;
    }
    __syncthreads();
    const int cutb = s_cut;
    const int cnt = s_hist[cutb];

    // ---- compact candidates into per-bin contiguous segments ----
    for (int f = t; f < RR; f += TPB) {
        float m = s_mag[f];
        int b = min((int)(m * inv), 255);
        if (b >= cutb) {
            int gs = (b < 255) ? s_hist[b + 1] : 0;   // segment start = count of greater bins
            int off = atomicAdd(&s_goff[b], 1);
            int pos = gs + off;
            s_ckey[pos] = (((unsigned long long)__float_as_uint(m)) << 10)
                        | (unsigned long long)(1023 - f);
            s_cbin[pos] = (unsigned char)b;
        }
    }
    __syncthreads();

    // ---- exact rank: segment start + within-bin pairwise count; scatter gains ----
    for (int i = t; i < cnt; i += TPB) {
        unsigned long long ki = s_ckey[i];
        int b  = s_cbin[i];
        int gs = (b < 255) ? s_hist[b + 1] : 0;
        int ge = gs + s_goff[b];
        int r  = gs;
        for (int j = gs; j < ge; ++j) r += (s_ckey[j] > ki) ? 1 : 0;
        if (r < kk) {
            int f = 1023 - (int)(ki & 1023ull);
            s_sc[f] = s_g[r];
        }
    }
    __syncthreads();

    // ---- pack scaled Hermitian spectrum for inverse (register staging; zb aliases hbuf head) ----
    float2* zb = (float2*)s_pool;   // padded complex buffer, PIDX indexing
    {
        const float2* h2 = (const float2*)hbuf;
        const float sc1 = 1.f / 1024.f;
        float2 st[2];
#pragma unroll
        for (int h = 0; h < 2; ++h) {
            int k  = t + h * 256;        // 0..511
            int km = NN - k;             // 512..1
            float2 Yk, Ym;
            if (k == 0) Yk = make_float2(hbuf[1], 0.f); else Yk = h2[k];
            if (km == 512) Ym = make_float2(hbuf[1024], 0.f); else Ym = h2[km];
            float a1 = s_sc[k];  Yk.x *= a1; Yk.y *= a1;
            float a2 = s_sc[km]; Ym.x *= a2; Ym.y *= a2;
            float px = Yk.x + Ym.x, py = Yk.y - Ym.y;
            float qx = Yk.x - Ym.x, qy = Yk.y + Ym.y;
            float2 w = s_tw[k];
            float tx = qx * w.x + qy * w.y;
            float ty = qy * w.x - qx * w.y;
            st[h] = make_float2(sc1 * (px - ty), sc1 * (py + tx));
        }
        __syncthreads();   // all hbuf reads complete before zb overwrites pool
#pragma unroll
        for (int h = 0; h < 2; ++h) {
            int k = t + h * 256;
            zb[PIDX(__brev(k) >> 23)] = st[h];
        }
    }
    __syncthreads();

    // ---- inverse 512-pt FFT: fused double radix-2 stages (1,2)(3,4)(5,6)(7,8) ----
#pragma unroll
    for (int lsp = 1; lsp <= 7; lsp += 2) {
        if (t < 128) {
            const int h1 = 1 << (lsp - 1);
            const int low = t & (h1 - 1);
            const int high = t >> (lsp - 1);
            const int bidx = low | (high << (lsp + 1));
            float2 z0 = zb[PIDX(bidx)];
            float2 z1 = zb[PIDX(bidx + h1)];
            float2 z2 = zb[PIDX(bidx + 2 * h1)];
            float2 z3 = zb[PIDX(bidx + 3 * h1)];
            float2 wa = s_tw[low << (10 - lsp)];
            int wbi = low << (9 - lsp);
            float2 wb = s_tw[wbi];
            float2 wc = s_tw[wbi + 256];
            float2 t1 = cmulc(z1, wa);
            float2 a0 = make_float2(z0.x + t1.x, z0.y + t1.y);
            float2 a1 = make_float2(z0.x - t1.x, z0.y - t1.y);
            float2 t2 = cmulc(z3, wa);
            float2 a2 = make_float2(z2.x + t2.x, z2.y + t2.y);
            float2 a3 = make_float2(z2.x - t2.x, z2.y - t2.y);
            float2 u = cmulc(a2, wb);
            float2 v = cmulc(a3, wc);
            zb[PIDX(bidx)]          = make_float2(a0.x + u.x, a0.y + u.y);
            zb[PIDX(bidx + h1)]     = make_float2(a1.x + v.x, a1.y + v.y);
            zb[PIDX(bidx + 2*h1)]   = make_float2(a0.x - u.x, a0.y - u.y);
            zb[PIDX(bidx + 3*h1)]   = make_float2(a1.x - v.x, a1.y - v.y);
        }
        __syncthreads();
    }

    // ---- final stage (ls=9) in registers, fused with bias add + gmem write ----
    {
        const float2* b2 = (const float2*)bias;
        float2* yr = (float2*)(y + row * DD);
        float2 u = zb[PIDX(t)];
        float2 v = zb[PIDX(t + 256)];
        float2 w = s_tw[t << 1];
        float2 vp = cmulc(v, w);
        float2 bb0 = b2[t];
        float2 bb1 = b2[t + 256];
        yr[t]       = make_float2(u.x + vp.x + bb0.x, u.y + vp.y + bb0.y);
        yr[t + 256] = make_float2(u.x - vp.x + bb1.x, u.y - vp.y + bb1.y);
    }
}

extern "C" void kernel_launch(void* const* d_in, const int* in_sizes, int n_in,
                              void* d_out, int out_size) {
    const float* x     = (const float*)d_in[0];
    const float* gains = (const float*)d_in[1];
    const float* bias  = (const float*)d_in[2];
    float* y = (float*)d_out;

    int rows = in_sizes[0] / DD;
    int kk = in_sizes[1];
    if (kk > KMAX) kk = KMAX;

    tw_init_kernel<<<3, 256>>>();
    spectral_kernel<<<rows, TPB>>>(x, gains, bias, y, kk);
}

// round 9
// speedup vs baseline: 1.9648x; 1.3396x over previous
#include <cuda_runtime.h>

#define DD 1024
#define NN 512
#define RR 513
#define TPB 256
#define KMAX 128
#define CKMAX 513

// padded index for inverse-FFT smem buffer (float2 units)
#define PIDX(i) ((i) + ((i) >> 4))
// padded index for forward-FFT intermediate buffers (float units)
#define FID(i) ((i) + ((i) >> 5))

// Twiddle table: g_tw[k] = (cos, -sin)(2*pi*k/1024), k=0..512, double-rounded to float.
__device__ float2 g_tw[RR];

__global__ void tw_init_kernel() {
    int i = blockIdx.x * blockDim.x + threadIdx.x;
    if (i < RR) {
        double a = (double)i / (double)NN;
        g_tw[i] = make_float2((float)cospi(a), (float)(-sinpi(a)));
    }
}

// XLA EmitHypot emulation in strict fp32 RN
__device__ __forceinline__ float xla_hypot(float re, float im) {
    float a = fabsf(re), b = fabsf(im);
    float mx = fmaxf(a, b), mn = fminf(a, b);
    if (mx == 0.f) return 0.f;
    float div = __fdiv_rn(mn, mx);
    float t = __fadd_rn(1.f, __fmul_rn(div, div));
    return __fmul_rn(mx, __fsqrt_rn(t));
}

// z * conj(w)  (free-form fp32; inverse path is not bit-constrained)
__device__ __forceinline__ float2 cmulc(float2 z, float2 w) {
    return make_float2(fmaf(z.x, w.x,  z.y * w.y),
                       fmaf(z.y, w.x, -z.x * w.y));
}

// ---- ducc/pocketfft radf4, bit-exact fp32 arithmetic, layout-flexible ----
// PIN/POUT: whether input/output buffers use the FID padded layout.
// Work order in section 2 is k-fastest (pure relabeling; same arithmetic DAG).
template<int PIN, int POUT>
__device__ __forceinline__ void radf4_pass(
    const float* __restrict__ cc, float* __restrict__ ch,
    const float2* __restrict__ tw, int ido, int l1, int m_step, int t, int osh)
{
#define RDX(i)    (PIN  ? cc[FID(i)] : cc[i])
#define WRX(i, v) do { if (POUT) ch[FID(i)] = (v); else ch[osh + (i)] = (v); } while (0)
    if (ido == 1) {
        if (t < l1) {
            int k = t;
            float c0 = RDX(k);
            float c1 = RDX(k + l1);
            float c2 = RDX(k + 2 * l1);
            float c3 = RDX(k + 3 * l1);
            float tr1 = c3 + c1;
            float tr2 = c0 + c2;
            WRX(4 * k,     tr2 + tr1);
            WRX(4 * k + 1, c0 - c2);
            WRX(4 * k + 2, c3 - c1);
            WRX(4 * k + 3, tr2 - tr1);
        }
        return;
    }
    // section 1: i=0
    if (t < l1) {
        int k = t;
        float c0 = RDX(ido * k);
        float c1 = RDX(ido * (k + l1));
        float c2 = RDX(ido * (k + 2 * l1));
        float c3 = RDX(ido * (k + 3 * l1));
        float tr1 = c3 + c1;
        float tr2 = c0 + c2;
        WRX(ido * (4 * k),               tr2 + tr1);
        WRX((ido - 1) + ido * (1 + 4*k), c0 - c2);
        WRX(ido * (2 + 4 * k),           c3 - c1);
        WRX((ido - 1) + ido * (3 + 4*k), tr2 - tr1);
    }
    const int nI = (ido >> 1) - 1;
    const int s2 = l1, e2 = l1 + l1 * nI;
    // section 2: complex butterflies with twiddles (k-fastest order)
    if (t >= s2 && t < e2) {
        int q = t - s2;
        int k = q % l1, ii = q / l1;
        int i = 2 + 2 * ii;
        int ic = ido - i;
        int m1 = (i >> 1) * m_step;
        float2 t1 = tw[m1], t2 = tw[2 * m1], t3 = tw[3 * m1];
        float w1r = t1.x, w1i = -t1.y;
        float w2r = t2.x, w2i = -t2.y;
        float w3r = t3.x, w3i = -t3.y;
        float ccr1 = RDX((i-1) + ido*(k + l1)),     cci1 = RDX(i + ido*(k + l1));
        float ccr2 = RDX((i-1) + ido*(k + 2*l1)),   cci2 = RDX(i + ido*(k + 2*l1));
        float ccr3 = RDX((i-1) + ido*(k + 3*l1)),   cci3 = RDX(i + ido*(k + 3*l1));
        float cr2 = __fadd_rn(__fmul_rn(w1r, ccr1), __fmul_rn(w1i, cci1));
        float ci2 = __fsub_rn(__fmul_rn(w1r, cci1), __fmul_rn(w1i, ccr1));
        float cr3 = __fadd_rn(__fmul_rn(w2r, ccr2), __fmul_rn(w2i, cci2));
        float ci3 = __fsub_rn(__fmul_rn(w2r, cci2), __fmul_rn(w2i, ccr2));
        float cr4 = __fadd_rn(__fmul_rn(w3r, ccr3), __fmul_rn(w3i, cci3));
        float ci4 = __fsub_rn(__fmul_rn(w3r, cci3), __fmul_rn(w3i, ccr3));
        float tr1 = cr4 + cr2, tr4 = cr4 - cr2;
        float ti1 = ci2 + ci4, ti4 = ci2 - ci4;
        float c0r = RDX((i-1) + ido*k), c0i = RDX(i + ido*k);
        float tr2 = c0r + cr3, tr3 = c0r - cr3;
        float ti2 = c0i + ci3, ti3 = c0i - ci3;
        WRX((i-1)  + ido*(4*k),     tr1 + tr2);
        WRX((ic-1) + ido*(3 + 4*k), tr2 - tr1);
        WRX(i      + ido*(4*k),     ti1 + ti2);
        WRX(ic     + ido*(3 + 4*k), ti1 - ti2);
        WRX((i-1)  + ido*(2 + 4*k), ti4 + tr3);
        WRX((ic-1) + ido*(1 + 4*k), tr3 - ti4);
        WRX(i      + ido*(2 + 4*k), tr4 + ti3);
        WRX(ic     + ido*(1 + 4*k), tr4 - ti3);
    }
    // section 3: tail i=ido
    if (t >= e2 && t < e2 + l1) {
        int k = t - e2;
        const float HS = 0.70710678118654752440f;
        float a  = RDX((ido-1) + ido*(k + l1));
        float b  = RDX((ido-1) + ido*(k + 3*l1));
        float cv = RDX((ido-1) + ido*(k + 2*l1));
        float c0 = RDX((ido-1) + ido*k);
        float ti1 = __fmul_rn(-HS, __fadd_rn(a, b));
        float tr1 = __fmul_rn( HS, __fsub_rn(a, b));
        WRX((ido-1) + ido*(4*k),     c0 + tr1);
        WRX((ido-1) + ido*(2 + 4*k), c0 - tr1);
        WRX(ido*(3 + 4*k),           ti1 + cv);
        WRX(ido*(1 + 4*k),           ti1 - cv);
    }
#undef RDX
#undef WRX
}

__global__ __launch_bounds__(TPB) void spectral_kernel(
    const float* __restrict__ x, const float* __restrict__ gains,
    const float* __restrict__ bias, float* __restrict__ y, int kk)
{
    // pool (floats): [0,1056) = input / B scratch (padded)
    //                [1056,2112) = A scratch (padded)
    //                [2112,3137) = H final halfcomplex (unpadded, osh=1)
    __shared__ __align__(16) float s_pool[3152];
    __shared__ float2 s_tw[RR];
    __shared__ float  s_mag[RR];
    __shared__ float  s_sc[RR];
    __shared__ float  s_g[KMAX];
    __shared__ int    s_hist[256];
    __shared__ int    s_goff[256];
    __shared__ unsigned long long s_ckey[CKMAX];
    __shared__ int    s_wsumi[8];
    __shared__ float  s_wmax[8];
    __shared__ int    s_cut;

    float* B = s_pool;            // also holds input (unpadded read by pass 1)
    float* A = s_pool + 1056;
    float* H = s_pool + 2112;

    const int t = threadIdx.x;
    const int lane = t & 31;
    const int wrp = t >> 5;
    const long long row = blockIdx.x;
    const float4* xr4 = (const float4*)(x + row * DD);

    for (int i = t; i < RR; i += TPB) s_tw[i] = g_tw[i];
    for (int i = t; i < kk; i += TPB) s_g[i] = gains[i];
    ((float4*)s_pool)[t] = xr4[t];
    __syncthreads();

    // ---- forward rfft: ducc radf4 x5, bit-exact fp32 (no contraction) ----
    radf4_pass<0,1>(B, A, s_tw,   1, 256, 256, t, 0); __syncthreads();
    radf4_pass<1,1>(A, B, s_tw,   4,  64,  64, t, 0); __syncthreads();
    radf4_pass<1,1>(B, A, s_tw,  16,  16,  16, t, 0); __syncthreads();
    radf4_pass<1,1>(A, B, s_tw,  64,   4,   4, t, 0); __syncthreads();
    radf4_pass<1,0>(B, H, s_tw, 256,   1,   1, t, 1); __syncthreads();
    // H (shift 1): X0 = H[1]; Xk = (H[2k], H[2k+1]) k=1..511; X512 = H[1024]

    // ---- magnitudes (XLA EmitHypot) ----
    {
        const float2* h2 = (const float2*)H;
#pragma unroll
        for (int h = 0; h < 2; ++h) {
            int k = t + h * 256;
            float xrf, xif;
            if (k == 0) { xrf = H[1]; xif = 0.f; }
            else        { float2 v = h2[k]; xrf = v.x; xif = v.y; }
            s_mag[k] = xla_hypot(xrf, xif);
            s_sc[k]  = 0.f;
        }
        if (t == 0) {
            s_mag[512] = xla_hypot(H[1024], 0.f);
            s_sc[512]  = 0.f;
        }
        s_hist[t] = 0;
        s_goff[t] = 0;
    }
    __syncthreads();

    // ---- max mag (block reduce) ----
    float mv = fmaxf(s_mag[t], s_mag[t + 256]);
    if (t == 0) mv = fmaxf(mv, s_mag[512]);
#pragma unroll
    for (int o = 16; o; o >>= 1) mv = fmaxf(mv, __shfl_xor_sync(0xffffffffu, mv, o));
    if (lane == 0) s_wmax[wrp] = mv;
    __syncthreads();
    if (t == 0) {
        float m2 = s_wmax[0];
#pragma unroll
        for (int i2 = 1; i2 < 8; ++i2) m2 = fmaxf(m2, s_wmax[i2]);
        s_wmax[0] = m2 * 1.0000002f + 1e-30f;
    }
    __syncthreads();

    const float hi = s_wmax[0];
    const float inv = 256.f / hi;

    // ---- single-pass histogram over [0, hi) ----
    for (int f = t; f < RR; f += TPB) {
        int b = min((int)(s_mag[f] * inv), 255);
        atomicAdd(&s_hist[b], 1);
    }
    __syncthreads();

    // ---- suffix scan (warp shuffles): s_hist[b] := count of elements in bins >= b ----
    {
        int v = s_hist[t];
#pragma unroll
        for (int d = 1; d < 32; d <<= 1) {
            int tmp = __shfl_down_sync(0xffffffffu, v, d);
            if (lane + d < 32) v += tmp;
        }
        if (lane == 0) s_wsumi[wrp] = v;
        __syncthreads();
        int add = 0;
#pragma unroll
        for (int w = 0; w < 8; ++w) add += (w > wrp) ? s_wsumi[w] : 0;
        v += add;
        s_hist[t] = v;
    }
    __syncthreads();

    // ---- cut bin: s_hist[cut] >= kk, s_hist[cut+1] < kk ----
    {
        int sa = s_hist[t];
        int sb = (t == 255) ? 0 : s_hist[t + 1];
        if (sa >= kk && sb < kk) s_cut = t;
    }
    __syncthreads();
    const int cutb = s_cut;
    const int cnt = s_hist[cutb];

    // ---- compact candidates into per-bin contiguous segments ----
    for (int f = t; f < RR; f += TPB) {
        float m = s_mag[f];
        int b = min((int)(m * inv), 255);
        if (b >= cutb) {
            int gs = (b < 255) ? s_hist[b + 1] : 0;
            int off = atomicAdd(&s_goff[b], 1);
            s_ckey[gs + off] = (((unsigned long long)__float_as_uint(m)) << 10)
                             | (unsigned long long)(1023 - f);
        }
    }
    __syncthreads();

    // ---- exact rank: segment start + within-bin pairwise count; scatter gains ----
    for (int i = t; i < cnt; i += TPB) {
        unsigned long long ki = s_ckey[i];
        float m = __uint_as_float((unsigned)(ki >> 10));
        int b = min((int)(m * inv), 255);
        int gs = (b < 255) ? s_hist[b + 1] : 0;
        int ge = gs + s_goff[b];
        int r  = gs;
        for (int j = gs; j < ge; ++j) r += (s_ckey[j] > ki) ? 1 : 0;
        if (r < kk) {
            int f = 1023 - (int)(ki & 1023ull);
            s_sc[f] = s_g[r];
        }
    }
    __syncthreads();

    // ---- pack scaled Hermitian spectrum for inverse (register staging) ----
    float2* zb = (float2*)s_pool;   // padded complex buffer [0,1088) floats; A/B dead
    {
        const float2* h2 = (const float2*)H;
        const float sc1 = 1.f / 1024.f;
        float2 st[2];
#pragma unroll
        for (int h = 0; h < 2; ++h) {
            int k  = t + h * 256;        // 0..511
            int km = NN - k;             // 512..1
            float2 Yk, Ym;
            if (k == 0) Yk = make_float2(H[1], 0.f); else Yk = h2[k];
            if (km == 512) Ym = make_float2(H[1024], 0.f); else Ym = h2[km];
            float a1 = s_sc[k];  Yk.x *= a1; Yk.y *= a1;
            float a2 = s_sc[km]; Ym.x *= a2; Ym.y *= a2;
            float px = Yk.x + Ym.x, py = Yk.y - Ym.y;
            float qx = Yk.x - Ym.x, qy = Yk.y + Ym.y;
            float2 w = s_tw[k];
            float tx = qx * w.x + qy * w.y;
            float ty = qy * w.x - qx * w.y;
            st[h] = make_float2(sc1 * (px - ty), sc1 * (py + tx));
        }
        __syncthreads();
#pragma unroll
        for (int h = 0; h < 2; ++h) {
            int k = t + h * 256;
            zb[PIDX(__brev(k) >> 23)] = st[h];
        }
    }
    __syncthreads();

    // ---- inverse 512-pt FFT: fused double radix-2 stages (1,2)(3,4)(5,6)(7,8) ----
#pragma unroll
    for (int lsp = 1; lsp <= 7; lsp += 2) {
        if (t < 128) {
            const int h1 = 1 << (lsp - 1);
            const int low = t & (h1 - 1);
            const int high = t >> (lsp - 1);
            const int bidx = low | (high << (lsp + 1));
            float2 z0 = zb[PIDX(bidx)];
            float2 z1 = zb[PIDX(bidx + h1)];
            float2 z2 = zb[PIDX(bidx + 2 * h1)];
            float2 z3 = zb[PIDX(bidx + 3 * h1)];
            float2 wa = s_tw[low << (10 - lsp)];
            int wbi = low << (9 - lsp);
            float2 wb = s_tw[wbi];
            float2 wc = s_tw[wbi + 256];
            float2 t1 = cmulc(z1, wa);
            float2 a0 = make_float2(z0.x + t1.x, z0.y + t1.y);
            float2 a1 = make_float2(z0.x - t1.x, z0.y - t1.y);
            float2 t2 = cmulc(z3, wa);
            float2 a2 = make_float2(z2.x + t2.x, z2.y + t2.y);
            float2 a3 = make_float2(z2.x - t2.x, z2.y - t2.y);
            float2 u = cmulc(a2, wb);
            float2 v = cmulc(a3, wc);
            zb[PIDX(bidx)]          = make_float2(a0.x + u.x, a0.y + u.y);
            zb[PIDX(bidx + h1)]     = make_float2(a1.x + v.x, a1.y + v.y);
            zb[PIDX(bidx + 2*h1)]   = make_float2(a0.x - u.x, a0.y - u.y);
            zb[PIDX(bidx + 3*h1)]   = make_float2(a1.x - v.x, a1.y - v.y);
        }
        __syncthreads();
    }

    // ---- final stage (ls=9) in registers, fused with bias add + gmem write ----
    {
        const float2* b2 = (const float2*)bias;
        float2* yr = (float2*)(y + row * DD);
        float2 u = zb[PIDX(t)];
        float2 v = zb[PIDX(t + 256)];
        float2 w = s_tw[t << 1];
        float2 vp = cmulc(v, w);
        float2 bb0 = b2[t];
        float2 bb1 = b2[t + 256];
        yr[t]       = make_float2(u.x + vp.x + bb0.x, u.y + vp.y + bb0.y);
        yr[t + 256] = make_float2(u.x - vp.x + bb1.x, u.y - vp.y + bb1.y);
    }
}

extern "C" void kernel_launch(void* const* d_in, const int* in_sizes, int n_in,
                              void* d_out, int out_size) {
    const float* x     = (const float*)d_in[0];
    const float* gains = (const float*)d_in[1];
    const float* bias  = (const float*)d_in[2];
    float* y = (float*)d_out;

    int rows = in_sizes[0] / DD;
    int kk = in_sizes[1];
    if (kk > KMAX) kk = KMAX;

    tw_init_kernel<<<3, 256>>>();
    spectral_kernel<<<rows, TPB>>>(x, gains, bias, y, kk);
}

// round 10
// speedup vs baseline: 2.0152x; 1.0256x over previous
#include <cuda_runtime.h>

#define DD 1024
#define NN 512
#define RR 513
#define TPB 256
#define KMAX 128
#define CKMAX 513

// padded index for inverse-FFT smem buffer (float2 units)
#define PIDX(i) ((i) + ((i) >> 4))
// padded index for forward-FFT intermediate buffers (float units; +2 per 32 keeps
// even indices even -> float2-aligned)
#define FD(i) ((i) + 2 * ((i) >> 5))

#define BSTRIDE 1092   // floats per padded buffer (FD(1024)=1088, rounded to /4)

// Twiddle table: g_tw[k] = (cos, -sin)(2*pi*k/1024), k=0..512, double-rounded to float.
__device__ float2 g_tw[RR];

__global__ void tw_init_kernel() {
    int i = blockIdx.x * blockDim.x + threadIdx.x;
    if (i < RR) {
        double a = (double)i / (double)NN;
        g_tw[i] = make_float2((float)cospi(a), (float)(-sinpi(a)));
    }
}

// XLA EmitHypot emulation in strict fp32 RN
__device__ __forceinline__ float xla_hypot(float re, float im) {
    float a = fabsf(re), b = fabsf(im);
    float mx = fmaxf(a, b), mn = fminf(a, b);
    if (mx == 0.f) return 0.f;
    float div = __fdiv_rn(mn, mx);
    float t = __fadd_rn(1.f, __fmul_rn(div, div));
    return __fmul_rn(mx, __fsqrt_rn(t));
}

// z * conj(w)  (free-form fp32; inverse path is not bit-constrained)
__device__ __forceinline__ float2 cmulc(float2 z, float2 w) {
    return make_float2(fmaf(z.x, w.x,  z.y * w.y),
                       fmaf(z.y, w.x, -z.x * w.y));
}

// ---- ducc/pocketfft radf4, bit-exact fp32 arithmetic ----
// All intermediate buffers use logical shift +1 (osh) + FD padding (PIN/POUT=1).
// Final pass (POUT=0) writes plain +1-shifted halfcomplex. Arithmetic DAG
// identical to the R6 passing kernel; only load/store shapes differ.
template<int PIN, int POUT>
__device__ __forceinline__ void radf4_pass(
    const float* __restrict__ cc, float* __restrict__ ch,
    const float2* __restrict__ tw, int ido, int l1, int m_step, int t)
{
#define RD1(i)    (PIN ? cc[FD((i) + 1)] : cc[i])
#define RD2(L)    (*(const float2*)&cc[FD((L) + 1)])
#define WR1(i, v) do { if (POUT) ch[FD((i) + 1)] = (v); else ch[1 + (i)] = (v); } while (0)
#define WR2(L, v) do { if (POUT) *(float2*)&ch[FD((L) + 1)] = (v); \
                       else      *(float2*)&ch[1 + (L)]     = (v); } while (0)
    if (ido == 1) {
        if (t < l1) {
            int k = t;
            float c0 = RD1(k);
            float c1 = RD1(k + l1);
            float c2 = RD1(k + 2 * l1);
            float c3 = RD1(k + 3 * l1);
            float tr1 = c3 + c1;
            float tr2 = c0 + c2;
            WR1(4 * k,     tr2 + tr1);
            WR2(4 * k + 1, make_float2(c0 - c2, c3 - c1));
            WR1(4 * k + 3, tr2 - tr1);
        }
        return;
    }
    // section 1: i=0
    if (t < l1) {
        int k = t;
        float c0 = RD1(ido * k);
        float c1 = RD1(ido * (k + l1));
        float c2 = RD1(ido * (k + 2 * l1));
        float c3 = RD1(ido * (k + 3 * l1));
        float tr1 = c3 + c1;
        float tr2 = c0 + c2;
        WR1(ido * (4 * k),               tr2 + tr1);
        WR1((ido - 1) + ido * (1 + 4*k), c0 - c2);
        WR1(ido * (2 + 4 * k),           c3 - c1);
        WR1((ido - 1) + ido * (3 + 4*k), tr2 - tr1);
    }
    const int nI = (ido >> 1) - 1;
    const int s2 = l1, e2 = l1 + l1 * nI;
    // section 2: complex butterflies with twiddles (k-fastest order)
    if (t >= s2 && t < e2) {
        int q = t - s2;
        int k = q % l1, ii = q / l1;
        int i = 2 + 2 * ii;
        int ic = ido - i;
        int m1 = (i >> 1) * m_step;
        float2 t1 = tw[m1], t2 = tw[2 * m1], t3 = tw[3 * m1];
        float w1r = t1.x, w1i = -t1.y;
        float w2r = t2.x, w2i = -t2.y;
        float w3r = t3.x, w3i = -t3.y;
        float2 cv1 = RD2((i-1) + ido*(k + l1));
        float2 cv2 = RD2((i-1) + ido*(k + 2*l1));
        float2 cv3 = RD2((i-1) + ido*(k + 3*l1));
        float ccr1 = cv1.x, cci1 = cv1.y;
        float ccr2 = cv2.x, cci2 = cv2.y;
        float ccr3 = cv3.x, cci3 = cv3.y;
        float cr2 = __fadd_rn(__fmul_rn(w1r, ccr1), __fmul_rn(w1i, cci1));
        float ci2 = __fsub_rn(__fmul_rn(w1r, cci1), __fmul_rn(w1i, ccr1));
        float cr3 = __fadd_rn(__fmul_rn(w2r, ccr2), __fmul_rn(w2i, cci2));
        float ci3 = __fsub_rn(__fmul_rn(w2r, cci2), __fmul_rn(w2i, ccr2));
        float cr4 = __fadd_rn(__fmul_rn(w3r, ccr3), __fmul_rn(w3i, cci3));
        float ci4 = __fsub_rn(__fmul_rn(w3r, cci3), __fmul_rn(w3i, ccr3));
        float tr1 = cr4 + cr2, tr4 = cr4 - cr2;
        float ti1 = ci2 + ci4, ti4 = ci2 - ci4;
        float2 c0v = RD2((i-1) + ido*k);
        float c0r = c0v.x, c0i = c0v.y;
        float tr2 = c0r + cr3, tr3 = c0r - cr3;
        float ti2 = c0i + ci3, ti3 = c0i - ci3;
        WR2((i-1)  + ido*(4*k),     make_float2(tr1 + tr2, ti1 + ti2));
        WR2((ic-1) + ido*(3 + 4*k), make_float2(tr2 - tr1, ti1 - ti2));
        WR2((i-1)  + ido*(2 + 4*k), make_float2(ti4 + tr3, tr4 + ti3));
        WR2((ic-1) + ido*(1 + 4*k), make_float2(tr3 - ti4, tr4 - ti3));
    }
    // section 3: tail i=ido
    if (t >= e2 && t < e2 + l1) {
        int k = t - e2;
        const float HS = 0.70710678118654752440f;
        float a  = RD1((ido-1) + ido*(k + l1));
        float b  = RD1((ido-1) + ido*(k + 3*l1));
        float cv = RD1((ido-1) + ido*(k + 2*l1));
        float c0 = RD1((ido-1) + ido*k);
        float ti1 = __fmul_rn(-HS, __fadd_rn(a, b));
        float tr1 = __fmul_rn( HS, __fsub_rn(a, b));
        WR1((ido-1) + ido*(4*k),     c0 + tr1);
        WR1((ido-1) + ido*(2 + 4*k), c0 - tr1);
        WR1(ido*(3 + 4*k),           ti1 + cv);
        WR1(ido*(1 + 4*k),           ti1 - cv);
    }
#undef RD1
#undef RD2
#undef WR1
#undef WR2
}

__global__ __launch_bounds__(TPB) void spectral_kernel(
    const float* __restrict__ x, const float* __restrict__ gains,
    const float* __restrict__ bias, float* __restrict__ y, int kk)
{
    // pool (floats): [0, 1092)       = B scratch (padded) / raw input / inverse zb
    //                [1092, 2184)    = A scratch (padded)
    //                [2184, 3209)    = H final halfcomplex (plain, shift 1)
    __shared__ __align__(16) float s_pool[3212];
    __shared__ float2 s_tw[RR];
    __shared__ float  s_mag[RR];
    __shared__ float  s_sc[RR];
    __shared__ float  s_g[KMAX];
    __shared__ int    s_hist[256];
    __shared__ int    s_goff[256];
    __shared__ unsigned long long s_ckey[CKMAX];
    __shared__ int    s_wsumi[8];
    __shared__ float  s_wmax[8];
    __shared__ int    s_cut;

    float* B = s_pool;
    float* A = s_pool + BSTRIDE;
    float* H = s_pool + 2 * BSTRIDE;

    const int t = threadIdx.x;
    const int lane = t & 31;
    const int wrp = t >> 5;
    const long long row = blockIdx.x;
    const float4* xr4 = (const float4*)(x + row * DD);

    for (int i = t; i < RR; i += TPB) s_tw[i] = g_tw[i];
    for (int i = t; i < kk; i += TPB) s_g[i] = gains[i];
    ((float4*)s_pool)[t] = xr4[t];
    __syncthreads();

    // ---- forward rfft: ducc radf4 x5, bit-exact fp32 (no contraction) ----
    radf4_pass<0,1>(B, A, s_tw,   1, 256, 256, t); __syncthreads();
    radf4_pass<1,1>(A, B, s_tw,   4,  64,  64, t); __syncthreads();
    radf4_pass<1,1>(B, A, s_tw,  16,  16,  16, t); __syncthreads();
    radf4_pass<1,1>(A, B, s_tw,  64,   4,   4, t); __syncthreads();
    radf4_pass<1,0>(B, H, s_tw, 256,   1,   1, t); __syncthreads();
    // H (shift 1): X0 = H[1]; Xk = (H[2k], H[2k+1]) k=1..511; X512 = H[1024]

    // ---- magnitudes (XLA EmitHypot) ----
    {
        const float2* h2 = (const float2*)H;
#pragma unroll
        for (int h = 0; h < 2; ++h) {
            int k = t + h * 256;
            float xrf, xif;
            if (k == 0) { xrf = H[1]; xif = 0.f; }
            else        { float2 v = h2[k]; xrf = v.x; xif = v.y; }
            s_mag[k] = xla_hypot(xrf, xif);
            s_sc[k]  = 0.f;
        }
        if (t == 0) {
            s_mag[512] = xla_hypot(H[1024], 0.f);
            s_sc[512]  = 0.f;
        }
        s_hist[t] = 0;
        s_goff[t] = 0;
    }
    __syncthreads();

    // ---- max mag (block reduce) ----
    float mv = fmaxf(s_mag[t], s_mag[t + 256]);
    if (t == 0) mv = fmaxf(mv, s_mag[512]);
#pragma unroll
    for (int o = 16; o; o >>= 1) mv = fmaxf(mv, __shfl_xor_sync(0xffffffffu, mv, o));
    if (lane == 0) s_wmax[wrp] = mv;
    __syncthreads();
    if (t == 0) {
        float m2 = s_wmax[0];
#pragma unroll
        for (int i2 = 1; i2 < 8; ++i2) m2 = fmaxf(m2, s_wmax[i2]);
        s_wmax[0] = m2 * 1.0000002f + 1e-30f;
    }
    __syncthreads();

    const float hi = s_wmax[0];
    const float inv = 256.f / hi;

    // ---- single-pass histogram over [0, hi) ----
    for (int f = t; f < RR; f += TPB) {
        int b = min((int)(s_mag[f] * inv), 255);
        atomicAdd(&s_hist[b], 1);
    }
    __syncthreads();

    // ---- suffix scan (warp shuffles): s_hist[b] := count of elements in bins >= b ----
    {
        int v = s_hist[t];
#pragma unroll
        for (int d = 1; d < 32; d <<= 1) {
            int tmp = __shfl_down_sync(0xffffffffu, v, d);
            if (lane + d < 32) v += tmp;
        }
        if (lane == 0) s_wsumi[wrp] = v;
        __syncthreads();
        int add = 0;
#pragma unroll
        for (int w = 0; w < 8; ++w) add += (w > wrp) ? s_wsumi[w] : 0;
        v += add;
        s_hist[t] = v;
    }
    __syncthreads();

    // ---- cut bin: s_hist[cut] >= kk, s_hist[cut+1] < kk ----
    {
        int sa = s_hist[t];
        int sb = (t == 255) ? 0 : s_hist[t + 1];
        if (sa >= kk && sb < kk) s_cut = t;
    }
    __syncthreads();
    const int cutb = s_cut;
    const int cnt = s_hist[cutb];

    // ---- compact candidates into per-bin contiguous segments ----
    for (int f = t; f < RR; f += TPB) {
        float m = s_mag[f];
        int b = min((int)(m * inv), 255);
        if (b >= cutb) {
            int gs = (b < 255) ? s_hist[b + 1] : 0;
            int off = atomicAdd(&s_goff[b], 1);
            s_ckey[gs + off] = (((unsigned long long)__float_as_uint(m)) << 10)
                             | (unsigned long long)(1023 - f);
        }
    }
    __syncthreads();

    // ---- exact rank: segment start + within-bin pairwise count; scatter gains ----
    for (int i = t; i < cnt; i += TPB) {
        unsigned long long ki = s_ckey[i];
        float m = __uint_as_float((unsigned)(ki >> 10));
        int b = min((int)(m * inv), 255);
        int gs = (b < 255) ? s_hist[b + 1] : 0;
        int ge = gs + s_goff[b];
        int r  = gs;
        for (int j = gs; j < ge; ++j) r += (s_ckey[j] > ki) ? 1 : 0;
        if (r < kk) {
            int f = 1023 - (int)(ki & 1023ull);
            s_sc[f] = s_g[r];
        }
    }
    __syncthreads();

    // ---- pack scaled Hermitian spectrum for inverse (zb = B region; H disjoint) ----
    float2* zb = (float2*)s_pool;
    {
        const float2* h2 = (const float2*)H;
        const float sc1 = 1.f / 1024.f;
#pragma unroll
        for (int h = 0; h < 2; ++h) {
            int k  = t + h * 256;        // 0..511
            int km = NN - k;             // 512..1
            float2 Yk, Ym;
            if (k == 0) Yk = make_float2(H[1], 0.f); else Yk = h2[k];
            if (km == 512) Ym = make_float2(H[1024], 0.f); else Ym = h2[km];
            float a1 = s_sc[k];  Yk.x *= a1; Yk.y *= a1;
            float a2 = s_sc[km]; Ym.x *= a2; Ym.y *= a2;
            float px = Yk.x + Ym.x, py = Yk.y - Ym.y;
            float qx = Yk.x - Ym.x, qy = Yk.y + Ym.y;
            float2 w = s_tw[k];
            float tx = qx * w.x + qy * w.y;
            float ty = qy * w.x - qx * w.y;
            zb[PIDX(__brev(k) >> 23)] = make_float2(sc1 * (px - ty), sc1 * (py + tx));
        }
    }
    __syncthreads();

    // ---- inverse 512-pt FFT: fused double radix-2 stages (1,2)(3,4)(5,6)(7,8) ----
#pragma unroll
    for (int lsp = 1; lsp <= 7; lsp += 2) {
        if (t < 128) {
            const int h1 = 1 << (lsp - 1);
            const int low = t & (h1 - 1);
            const int high = t >> (lsp - 1);
            const int bidx = low | (high << (lsp + 1));
            float2 z0 = zb[PIDX(bidx)];
            float2 z1 = zb[PIDX(bidx + h1)];
            float2 z2 = zb[PIDX(bidx + 2 * h1)];
            float2 z3 = zb[PIDX(bidx + 3 * h1)];
            float2 wa = s_tw[low << (10 - lsp)];
            int wbi = low << (9 - lsp);
            float2 wb = s_tw[wbi];
            float2 wc = s_tw[wbi + 256];
            float2 t1 = cmulc(z1, wa);
            float2 a0 = make_float2(z0.x + t1.x, z0.y + t1.y);
            float2 a1 = make_float2(z0.x - t1.x, z0.y - t1.y);
            float2 t2 = cmulc(z3, wa);
            float2 a2 = make_float2(z2.x + t2.x, z2.y + t2.y);
            float2 a3 = make_float2(z2.x - t2.x, z2.y - t2.y);
            float2 u = cmulc(a2, wb);
            float2 v = cmulc(a3, wc);
            zb[PIDX(bidx)]          = make_float2(a0.x + u.x, a0.y + u.y);
            zb[PIDX(bidx + h1)]     = make_float2(a1.x + v.x, a1.y + v.y);
            zb[PIDX(bidx + 2*h1)]   = make_float2(a0.x - u.x, a0.y - u.y);
            zb[PIDX(bidx + 3*h1)]   = make_float2(a1.x - v.x, a1.y - v.y);
        }
        __syncthreads();
    }

    // ---- final stage (ls=9) in registers, fused with bias add + gmem write ----
    {
        const float2* b2 = (const float2*)bias;
        float2* yr = (float2*)(y + row * DD);
        float2 u = zb[PIDX(t)];
        float2 v = zb[PIDX(t + 256)];
        float2 w = s_tw[t << 1];
        float2 vp = cmulc(v, w);
        float2 bb0 = b2[t];
        float2 bb1 = b2[t + 256];
        yr[t]       = make_float2(u.x + vp.x + bb0.x, u.y + vp.y + bb0.y);
        yr[t + 256] = make_float2(u.x - vp.x + bb1.x, u.y - vp.y + bb1.y);
    }
}

extern "C" void kernel_launch(void* const* d_in, const int* in_sizes, int n_in,
                              void* d_out, int out_size) {
    const float* x     = (const float*)d_in[0];
    const float* gains = (const float*)d_in[1];
    const float* bias  = (const float*)d_in[2];
    float* y = (float*)d_out;

    int rows = in_sizes[0] / DD;
    int kk = in_sizes[1];
    if (kk > KMAX) kk = KMAX;

    tw_init_kernel<<<3, 256>>>();
    spectral_kernel<<<rows, TPB>>>(x, gains, bias, y, kk);
}

// round 11
// speedup vs baseline: 2.0156x; 1.0002x over previous
#include <cuda_runtime.h>

#define DD 1024
#define NN 512
#define RR 513
#define TPB 256
#define KMAX 128
#define CKMAX 513

// padded index for inverse-FFT smem buffer (float2 units)
#define PIDX(i) ((i) + ((i) >> 4))
// per-life pads for forward scratch (float units; +2 steps keep float2 alignment)
// P==1: +2 per 32 (conflict-free for lane-stride 4/16)
// P==2: +2 per 64 (conflict-free for lane-stride 64/256)
#define FDX(P, i) ((P) == 1 ? (i) + 2 * ((i) >> 5) : \
                   (P) == 2 ? (i) + 2 * ((i) >> 6) : (i))

#define BSTRIDE 1092   // floats per padded buffer (max pad of 1025 floats, /4 aligned)

// Twiddle table: g_tw[k] = (cos, -sin)(2*pi*k/1024), k=0..512, double-rounded to float.
__device__ float2 g_tw[RR];

__global__ void tw_init_kernel() {
    int i = blockIdx.x * blockDim.x + threadIdx.x;
    if (i < RR) {
        double a = (double)i / (double)NN;
        g_tw[i] = make_float2((float)cospi(a), (float)(-sinpi(a)));
    }
}

// XLA EmitHypot emulation in strict fp32 RN
__device__ __forceinline__ float xla_hypot(float re, float im) {
    float a = fabsf(re), b = fabsf(im);
    float mx = fmaxf(a, b), mn = fminf(a, b);
    if (mx == 0.f) return 0.f;
    float div = __fdiv_rn(mn, mx);
    float t = __fadd_rn(1.f, __fmul_rn(div, div));
    return __fmul_rn(mx, __fsqrt_rn(t));
}

// z * conj(w)  (free-form fp32; inverse path is not bit-constrained)
__device__ __forceinline__ float2 cmulc(float2 z, float2 w) {
    return make_float2(fmaf(z.x, w.x,  z.y * w.y),
                       fmaf(z.y, w.x, -z.x * w.y));
}

// ---- ducc/pocketfft radf4, bit-exact fp32 arithmetic ----
// PIN/POUT select the buffer-life pad (0 = raw input read / plain +1-shift write).
// Arithmetic DAG identical to the R6 passing kernel; only addresses differ.
template<int PIN, int POUT>
__device__ __forceinline__ void radf4_pass(
    const float* __restrict__ cc, float* __restrict__ ch,
    const float2* __restrict__ tw, int ido, int l1, int m_step, int t)
{
#define RD1(i)    (PIN ? cc[FDX(PIN, (i) + 1)] : cc[i])
#define RD2(L)    (*(const float2*)&cc[FDX(PIN, (L) + 1)])
#define WR1(i, v) do { if (POUT) ch[FDX(POUT, (i) + 1)] = (v); else ch[1 + (i)] = (v); } while (0)
#define WR2(L, v) do { if (POUT) *(float2*)&ch[FDX(POUT, (L) + 1)] = (v); \
                       else      *(float2*)&ch[1 + (L)]            = (v); } while (0)
    if (ido == 1) {
        if (t < l1) {
            int k = t;
            float c0 = RD1(k);
            float c1 = RD1(k + l1);
            float c2 = RD1(k + 2 * l1);
            float c3 = RD1(k + 3 * l1);
            float tr1 = c3 + c1;
            float tr2 = c0 + c2;
            WR1(4 * k,     tr2 + tr1);
            WR2(4 * k + 1, make_float2(c0 - c2, c3 - c1));
            WR1(4 * k + 3, tr2 - tr1);
        }
        return;
    }
    // section 1: i=0
    if (t < l1) {
        int k = t;
        float c0 = RD1(ido * k);
        float c1 = RD1(ido * (k + l1));
        float c2 = RD1(ido * (k + 2 * l1));
        float c3 = RD1(ido * (k + 3 * l1));
        float tr1 = c3 + c1;
        float tr2 = c0 + c2;
        WR1(ido * (4 * k),               tr2 + tr1);
        WR1((ido - 1) + ido * (1 + 4*k), c0 - c2);
        WR1(ido * (2 + 4 * k),           c3 - c1);
        WR1((ido - 1) + ido * (3 + 4*k), tr2 - tr1);
    }
    const int nI = (ido >> 1) - 1;
    const int s2 = l1, e2 = l1 + l1 * nI;
    // section 2: complex butterflies with twiddles (k-fastest order)
    if (t >= s2 && t < e2) {
        int q = t - s2;
        int k = q % l1, ii = q / l1;
        int i = 2 + 2 * ii;
        int ic = ido - i;
        int m1 = (i >> 1) * m_step;
        float2 t1 = tw[m1], t2 = tw[2 * m1], t3 = tw[3 * m1];
        float w1r = t1.x, w1i = -t1.y;
        float w2r = t2.x, w2i = -t2.y;
        float w3r = t3.x, w3i = -t3.y;
        float2 cv1 = RD2((i-1) + ido*(k + l1));
        float2 cv2 = RD2((i-1) + ido*(k + 2*l1));
        float2 cv3 = RD2((i-1) + ido*(k + 3*l1));
        float ccr1 = cv1.x, cci1 = cv1.y;
        float ccr2 = cv2.x, cci2 = cv2.y;
        float ccr3 = cv3.x, cci3 = cv3.y;
        float cr2 = __fadd_rn(__fmul_rn(w1r, ccr1), __fmul_rn(w1i, cci1));
        float ci2 = __fsub_rn(__fmul_rn(w1r, cci1), __fmul_rn(w1i, ccr1));
        float cr3 = __fadd_rn(__fmul_rn(w2r, ccr2), __fmul_rn(w2i, cci2));
        float ci3 = __fsub_rn(__fmul_rn(w2r, cci2), __fmul_rn(w2i, ccr2));
        float cr4 = __fadd_rn(__fmul_rn(w3r, ccr3), __fmul_rn(w3i, cci3));
        float ci4 = __fsub_rn(__fmul_rn(w3r, cci3), __fmul_rn(w3i, ccr3));
        float tr1 = cr4 + cr2, tr4 = cr4 - cr2;
        float ti1 = ci2 + ci4, ti4 = ci2 - ci4;
        float2 c0v = RD2((i-1) + ido*k);
        float c0r = c0v.x, c0i = c0v.y;
        float tr2 = c0r + cr3, tr3 = c0r - cr3;
        float ti2 = c0i + ci3, ti3 = c0i - ci3;
        WR2((i-1)  + ido*(4*k),     make_float2(tr1 + tr2, ti1 + ti2));
        WR2((ic-1) + ido*(3 + 4*k), make_float2(tr2 - tr1, ti1 - ti2));
        WR2((i-1)  + ido*(2 + 4*k), make_float2(ti4 + tr3, tr4 + ti3));
        WR2((ic-1) + ido*(1 + 4*k), make_float2(tr3 - ti4, tr4 - ti3));
    }
    // section 3: tail i=ido
    if (t >= e2 && t < e2 + l1) {
        int k = t - e2;
        const float HS = 0.70710678118654752440f;
        float a  = RD1((ido-1) + ido*(k + l1));
        float b  = RD1((ido-1) + ido*(k + 3*l1));
        float cv = RD1((ido-1) + ido*(k + 2*l1));
        float c0 = RD1((ido-1) + ido*k);
        float ti1 = __fmul_rn(-HS, __fadd_rn(a, b));
        float tr1 = __fmul_rn( HS, __fsub_rn(a, b));
        WR1((ido-1) + ido*(4*k),     c0 + tr1);
        WR1((ido-1) + ido*(2 + 4*k), c0 - tr1);
        WR1(ido*(3 + 4*k),           ti1 + cv);
        WR1(ido*(1 + 4*k),           ti1 - cv);
    }
#undef RD1
#undef RD2
#undef WR1
#undef WR2
}

__global__ __launch_bounds__(TPB) void spectral_kernel(
    const float* __restrict__ x, const float* __restrict__ gains,
    const float* __restrict__ bias, float* __restrict__ y, int kk)
{
    // pool (floats): [0, 1092)    = B scratch / raw input / inverse zb
    //                [1092, 2184) = A scratch
    //                [2184, 3209) = H final halfcomplex (plain, shift 1)
    __shared__ __align__(16) float s_pool[3212];
    __shared__ float2 s_tw[RR];
    __shared__ float  s_mag[RR];
    __shared__ float  s_sc[RR];
    __shared__ float  s_g[KMAX];
    __shared__ int    s_hist[256];
    __shared__ int    s_goff[256];
    __shared__ unsigned long long s_ckey[CKMAX];
    __shared__ int    s_wsumi[8];
    __shared__ float  s_wmax[8];
    __shared__ int    s_cut;

    float* B = s_pool;
    float* A = s_pool + BSTRIDE;
    float* H = s_pool + 2 * BSTRIDE;

    const int t = threadIdx.x;
    const int lane = t & 31;
    const int wrp = t >> 5;
    const long long row = blockIdx.x;
    const float4* xr4 = (const float4*)(x + row * DD);

    for (int i = t; i < RR; i += TPB) s_tw[i] = g_tw[i];
    for (int i = t; i < kk; i += TPB) s_g[i] = gains[i];
    ((float4*)s_pool)[t] = xr4[t];     // raw, unpadded (pass-1 reads lane-stride 1)
    __syncthreads();

    // ---- forward rfft: ducc radf4 x5, bit-exact fp32 (no contraction) ----
    // pads per buffer life: A life1 = 1, B life1 = 1, A life2 = 2, B life2 = 2
    radf4_pass<0,1>(B, A, s_tw,   1, 256, 256, t); __syncthreads();
    radf4_pass<1,1>(A, B, s_tw,   4,  64,  64, t); __syncthreads();
    radf4_pass<1,2>(B, A, s_tw,  16,  16,  16, t); __syncthreads();
    radf4_pass<2,2>(A, B, s_tw,  64,   4,   4, t); __syncthreads();
    radf4_pass<2,0>(B, H, s_tw, 256,   1,   1, t); __syncthreads();
    // H (shift 1): X0 = H[1]; Xk = (H[2k], H[2k+1]) k=1..511; X512 = H[1024]

    // ---- magnitudes (XLA EmitHypot) ----
    {
        const float2* h2 = (const float2*)H;
#pragma unroll
        for (int h = 0; h < 2; ++h) {
            int k = t + h * 256;
            float xrf, xif;
            if (k == 0) { xrf = H[1]; xif = 0.f; }
            else        { float2 v = h2[k]; xrf = v.x; xif = v.y; }
            s_mag[k] = xla_hypot(xrf, xif);
            s_sc[k]  = 0.f;
        }
        if (t == 0) {
            s_mag[512] = xla_hypot(H[1024], 0.f);
            s_sc[512]  = 0.f;
        }
        s_hist[t] = 0;
        s_goff[t] = 0;
    }
    __syncthreads();

    // ---- max mag (block reduce) ----
    float mv = fmaxf(s_mag[t], s_mag[t + 256]);
    if (t == 0) mv = fmaxf(mv, s_mag[512]);
#pragma unroll
    for (int o = 16; o; o >>= 1) mv = fmaxf(mv, __shfl_xor_sync(0xffffffffu, mv, o));
    if (lane == 0) s_wmax[wrp] = mv;
    __syncthreads();
    if (t == 0) {
        float m2 = s_wmax[0];
#pragma unroll
        for (int i2 = 1; i2 < 8; ++i2) m2 = fmaxf(m2, s_wmax[i2]);
        s_wmax[0] = m2 * 1.0000002f + 1e-30f;
    }
    __syncthreads();

    const float hi = s_wmax[0];
    const float inv = 256.f / hi;

    // ---- single-pass histogram over [0, hi) ----
    for (int f = t; f < RR; f += TPB) {
        int b = min((int)(s_mag[f] * inv), 255);
        atomicAdd(&s_hist[b], 1);
    }
    __syncthreads();

    // ---- suffix scan (warp shuffles): s_hist[b] := count of elements in bins >= b ----
    {
        int v = s_hist[t];
#pragma unroll
        for (int d = 1; d < 32; d <<= 1) {
            int tmp = __shfl_down_sync(0xffffffffu, v, d);
            if (lane + d < 32) v += tmp;
        }
        if (lane == 0) s_wsumi[wrp] = v;
        __syncthreads();
        int add = 0;
#pragma unroll
        for (int w = 0; w < 8; ++w) add += (w > wrp) ? s_wsumi[w] : 0;
        v += add;
        s_hist[t] = v;
    }
    __syncthreads();

    // ---- cut bin: s_hist[cut] >= kk, s_hist[cut+1] < kk ----
    {
        int sa = s_hist[t];
        int sb = (t == 255) ? 0 : s_hist[t + 1];
        if (sa >= kk && sb < kk) s_cut = t;
    }
    __syncthreads();
    const int cutb = s_cut;
    const int cnt = s_hist[cutb];

    // ---- compact candidates into per-bin contiguous segments ----
    for (int f = t; f < RR; f += TPB) {
        float m = s_mag[f];
        int b = min((int)(m * inv), 255);
        if (b >= cutb) {
            int gs = (b < 255) ? s_hist[b + 1] : 0;
            int off = atomicAdd(&s_goff[b], 1);
            s_ckey[gs + off] = (((unsigned long long)__float_as_uint(m)) << 10)
                             | (unsigned long long)(1023 - f);
        }
    }
    __syncthreads();

    // ---- exact rank: segment start + within-bin pairwise count; scatter gains ----
    for (int i = t; i < cnt; i += TPB) {
        unsigned long long ki = s_ckey[i];
        float m = __uint_as_float((unsigned)(ki >> 10));
        int b = min((int)(m * inv), 255);
        int gs = (b < 255) ? s_hist[b + 1] : 0;
        int ge = gs + s_goff[b];
        int r  = gs;
        for (int j = gs; j < ge; ++j) r += (s_ckey[j] > ki) ? 1 : 0;
        if (r < kk) {
            int f = 1023 - (int)(ki & 1023ull);
            s_sc[f] = s_g[r];
        }
    }
    __syncthreads();

    // ---- pack scaled Hermitian spectrum for inverse (zb = B region; H disjoint) ----
    float2* zb = (float2*)s_pool;
    {
        const float2* h2 = (const float2*)H;
        const float sc1 = 1.f / 1024.f;
#pragma unroll
        for (int h = 0; h < 2; ++h) {
            int k  = t + h * 256;        // 0..511
            int km = NN - k;             // 512..1
            float2 Yk, Ym;
            if (k == 0) Yk = make_float2(H[1], 0.f); else Yk = h2[k];
            if (km == 512) Ym = make_float2(H[1024], 0.f); else Ym = h2[km];
            float a1 = s_sc[k];  Yk.x *= a1; Yk.y *= a1;
            float a2 = s_sc[km]; Ym.x *= a2; Ym.y *= a2;
            float px = Yk.x + Ym.x, py = Yk.y - Ym.y;
            float qx = Yk.x - Ym.x, qy = Yk.y + Ym.y;
            float2 w = s_tw[k];
            float tx = qx * w.x + qy * w.y;
            float ty = qy * w.x - qx * w.y;
            zb[PIDX(__brev(k) >> 23)] = make_float2(sc1 * (px - ty), sc1 * (py + tx));
        }
    }
    __syncthreads();

    // ---- inverse 512-pt FFT: fused double radix-2 stages (1,2)(3,4)(5,6)(7,8) ----
#pragma unroll
    for (int lsp = 1; lsp <= 7; lsp += 2) {
        if (t < 128) {
            const int h1 = 1 << (lsp - 1);
            const int low = t & (h1 - 1);
            const int high = t >> (lsp - 1);
            const int bidx = low | (high << (lsp + 1));
            float2 z0 = zb[PIDX(bidx)];
            float2 z1 = zb[PIDX(bidx + h1)];
            float2 z2 = zb[PIDX(bidx + 2 * h1)];
            float2 z3 = zb[PIDX(bidx + 3 * h1)];
            float2 wa = s_tw[low << (10 - lsp)];
            int wbi = low << (9 - lsp);
            float2 wb = s_tw[wbi];
            float2 wc = s_tw[wbi + 256];
            float2 t1 = cmulc(z1, wa);
            float2 a0 = make_float2(z0.x + t1.x, z0.y + t1.y);
            float2 a1 = make_float2(z0.x - t1.x, z0.y - t1.y);
            float2 t2 = cmulc(z3, wa);
            float2 a2 = make_float2(z2.x + t2.x, z2.y + t2.y);
            float2 a3 = make_float2(z2.x - t2.x, z2.y - t2.y);
            float2 u = cmulc(a2, wb);
            float2 v = cmulc(a3, wc);
            zb[PIDX(bidx)]          = make_float2(a0.x + u.x, a0.y + u.y);
            zb[PIDX(bidx + h1)]     = make_float2(a1.x + v.x, a1.y + v.y);
            zb[PIDX(bidx + 2*h1)]   = make_float2(a0.x - u.x, a0.y - u.y);
            zb[PIDX(bidx + 3*h1)]   = make_float2(a1.x - v.x, a1.y - v.y);
        }
        __syncthreads();
    }

    // ---- final stage (ls=9) in registers, fused with bias add + gmem write ----
    {
        const float2* b2 = (const float2*)bias;
        float2* yr = (float2*)(y + row * DD);
        float2 u = zb[PIDX(t)];
        float2 v = zb[PIDX(t + 256)];
        float2 w = s_tw[t << 1];
        float2 vp = cmulc(v, w);
        float2 bb0 = b2[t];
        float2 bb1 = b2[t + 256];
        yr[t]       = make_float2(u.x + vp.x + bb0.x, u.y + vp.y + bb0.y);
        yr[t + 256] = make_float2(u.x - vp.x + bb1.x, u.y - vp.y + bb1.y);
    }
}

extern "C" void kernel_launch(void* const* d_in, const int* in_sizes, int n_in,
                              void* d_out, int out_size) {
    const float* x     = (const float*)d_in[0];
    const float* gains = (const float*)d_in[1];
    const float* bias  = (const float*)d_in[2];
    float* y = (float*)d_out;

    int rows = in_sizes[0] / DD;
    int kk = in_sizes[1];
    if (kk > KMAX) kk = KMAX;

    tw_init_kernel<<<3, 256>>>();
    spectral_kernel<<<rows, TPB>>>(x, gains, bias, y, kk);
}

// round 13
// speedup vs baseline: 2.0658x; 1.0249x over previous
#include <cuda_runtime.h>

#define DD 1024
#define NN 512
#define RR 513
#define TPB 256
#define KMAX 128
#define CKMAX 513

// padded index for inverse-FFT smem buffer (float2 units)
#define PIDX(i) ((i) + ((i) >> 4))
// per-life pads for forward scratch (float units; +2 steps keep float2 alignment)
#define FDX(P, i) ((P) == 1 ? (i) + 2 * ((i) >> 5) : \
                   (P) == 2 ? (i) + 2 * ((i) >> 6) : (i))

#define BSTRIDE 1092

// Twiddle table: g_tw[k] = (cos, -sin)(2*pi*k/1024), k=0..512, double-rounded to float.
__device__ float2 g_tw[RR];

__global__ void tw_init_kernel() {
    int i = blockIdx.x * blockDim.x + threadIdx.x;
    if (i < RR) {
        double a = (double)i / (double)NN;
        g_tw[i] = make_float2((float)cospi(a), (float)(-sinpi(a)));
    }
}

__device__ __forceinline__ float xla_hypot(float re, float im) {
    float a = fabsf(re), b = fabsf(im);
    float mx = fmaxf(a, b), mn = fminf(a, b);
    if (mx == 0.f) return 0.f;
    float div = __fdiv_rn(mn, mx);
    float t = __fadd_rn(1.f, __fmul_rn(div, div));
    return __fmul_rn(mx, __fsqrt_rn(t));
}

__device__ __forceinline__ float2 cmulc(float2 z, float2 w) {
    return make_float2(fmaf(z.x, w.x,  z.y * w.y),
                       fmaf(z.y, w.x, -z.x * w.y));
}

// ---- bit-exact radf4 butterfly helpers (same arithmetic as R6 passing kernel) ----
__device__ __forceinline__ float4 r4_real(float c0, float c1, float c2, float c3) {
    float tr1 = c3 + c1, tr2 = c0 + c2;
    return make_float4(tr2 + tr1, c0 - c2, c3 - c1, tr2 - tr1);
}
__device__ __forceinline__ float4 r4_tail(float c0, float a, float cv, float b) {
    const float HS = 0.70710678118654752440f;
    float ti1 = __fmul_rn(-HS, __fadd_rn(a, b));
    float tr1 = __fmul_rn( HS, __fsub_rn(a, b));
    return make_float4(c0 + tr1, ti1 - cv, c0 - tr1, ti1 + cv);
}
struct R4C { float2 o0, o1, o2, o3; };  // o0@(i)j0, o1@(ic)j1, o2@(i)j2, o3@(ic)j3
__device__ __forceinline__ R4C r4_cplx(float2 c0v, float2 cv1, float2 cv2, float2 cv3,
                                       float2 t1, float2 t2, float2 t3) {
    float w1r = t1.x, w1i = -t1.y;
    float w2r = t2.x, w2i = -t2.y;
    float w3r = t3.x, w3i = -t3.y;
    float cr2 = __fadd_rn(__fmul_rn(w1r, cv1.x), __fmul_rn(w1i, cv1.y));
    float ci2 = __fsub_rn(__fmul_rn(w1r, cv1.y), __fmul_rn(w1i, cv1.x));
    float cr3 = __fadd_rn(__fmul_rn(w2r, cv2.x), __fmul_rn(w2i, cv2.y));
    float ci3 = __fsub_rn(__fmul_rn(w2r, cv2.y), __fmul_rn(w2i, cv2.x));
    float cr4 = __fadd_rn(__fmul_rn(w3r, cv3.x), __fmul_rn(w3i, cv3.y));
    float ci4 = __fsub_rn(__fmul_rn(w3r, cv3.y), __fmul_rn(w3i, cv3.x));
    float tr1 = cr4 + cr2, tr4 = cr4 - cr2;
    float ti1 = ci2 + ci4, ti4 = ci2 - ci4;
    float tr2 = c0v.x + cr3, tr3 = c0v.x - cr3;
    float ti2 = c0v.y + ci3, ti3 = c0v.y - ci3;
    R4C r;
    r.o0 = make_float2(tr1 + tr2, ti1 + ti2);
    r.o3 = make_float2(tr2 - tr1, ti1 - ti2);
    r.o2 = make_float2(ti4 + tr3, tr4 + ti3);
    r.o1 = make_float2(tr3 - ti4, tr4 - ti3);
    return r;
}

// ---- generic radf4 middle pass (used only for pass 3: B(P1) -> A(P2)) ----
template<int PIN, int POUT>
__device__ __forceinline__ void radf4_pass(
    const float* __restrict__ cc, float* __restrict__ ch,
    const float2* __restrict__ tw, int ido, int l1, int m_step, int t)
{
#define RD1(i)    cc[FDX(PIN, (i) + 1)]
#define RD2(L)    (*(const float2*)&cc[FDX(PIN, (L) + 1)])
#define WR1(i, v) do { ch[FDX(POUT, (i) + 1)] = (v); } while (0)
#define WR2(L, v) do { *(float2*)&ch[FDX(POUT, (L) + 1)] = (v); } while (0)
    if (t < l1) {
        int k = t;
        float4 r = r4_real(RD1(ido * k), RD1(ido * (k + l1)),
                           RD1(ido * (k + 2 * l1)), RD1(ido * (k + 3 * l1)));
        WR1(ido * (4 * k),               r.x);
        WR1((ido - 1) + ido * (1 + 4*k), r.y);
        WR1(ido * (2 + 4 * k),           r.z);
        WR1((ido - 1) + ido * (3 + 4*k), r.w);
    }
    const int nI = (ido >> 1) - 1;
    const int s2 = l1, e2 = l1 + l1 * nI;
    if (t >= s2 && t < e2) {
        int q = t - s2;
        int k = q % l1, ii = q / l1;
        int i = 2 + 2 * ii;
        int ic = ido - i;
        int m1 = (i >> 1) * m_step;
        R4C r = r4_cplx(RD2((i-1) + ido*k),
                        RD2((i-1) + ido*(k + l1)),
                        RD2((i-1) + ido*(k + 2*l1)),
                        RD2((i-1) + ido*(k + 3*l1)),
                        tw[m1], tw[2*m1], tw[3*m1]);
        WR2((i-1)  + ido*(4*k),     r.o0);
        WR2((ic-1) + ido*(3 + 4*k), r.o3);
        WR2((i-1)  + ido*(2 + 4*k), r.o2);
        WR2((ic-1) + ido*(1 + 4*k), r.o1);
    }
    if (t >= e2 && t < e2 + l1) {
        int k = t - e2;
        float4 r = r4_tail(RD1((ido-1) + ido*k), RD1((ido-1) + ido*(k + l1)),
                           RD1((ido-1) + ido*(k + 2*l1)), RD1((ido-1) + ido*(k + 3*l1)));
        WR1((ido-1) + ido*(4*k),     r.x);
        WR1(ido*(1 + 4*k),           r.y);
        WR1((ido-1) + ido*(2 + 4*k), r.z);
        WR1(ido*(3 + 4*k),           r.w);
    }
#undef RD1
#undef RD2
#undef WR1
#undef WR2
}

__global__ __launch_bounds__(TPB, 8) void spectral_kernel(
    const float* __restrict__ x, const float* __restrict__ gains,
    const float* __restrict__ bias, float* __restrict__ y, int kk)
{
    __shared__ __align__(16) float s_pool[3212];
    __shared__ float2 s_tw[RR];
    __shared__ float  s_mag[RR];
    __shared__ float  s_sc[RR];
    __shared__ float  s_g[KMAX];
    __shared__ int    s_hist[256];
    __shared__ int    s_goff[256];
    __shared__ unsigned long long s_ckey[CKMAX];
    __shared__ int    s_wsumi[8];
    __shared__ float  s_wmax[8];
    __shared__ int    s_cut;

    float* B = s_pool;
    float* A = s_pool + BSTRIDE;
    float* H = s_pool + 2 * BSTRIDE;

    const int t = threadIdx.x;
    const int lane = t & 31;
    const int wrp = t >> 5;
    const long long row = blockIdx.x;
    const float* xrow = x + row * DD;

    for (int i = t; i < RR; i += TPB) s_tw[i] = g_tw[i];
    for (int i = t; i < kk; i += TPB) s_g[i] = gains[i];
    __syncthreads();

    // ================= forward rfft: ducc radf4 x5, bit-exact, fused =================
    // ---- fused pass 1+2 : gmem -> B(P1). thread k2 = t in [0,64) ----
    if (t < 64) {
        const int k2 = t;
        float q[4][4];
#pragma unroll
        for (int m = 0; m < 4; ++m) {
            int base = k2 + 64 * m;
            float4 r = r4_real(xrow[base], xrow[base + 256],
                               xrow[base + 512], xrow[base + 768]);
            q[m][0] = r.x; q[m][1] = r.y; q[m][2] = r.z; q[m][3] = r.w;
        }
        float out[16];
        {   // pass-2 sect1 (i=0)
            float4 r = r4_real(q[0][0], q[1][0], q[2][0], q[3][0]);
            out[0] = r.x; out[7] = r.y; out[8] = r.z; out[15] = r.w;
        }
        {   // pass-2 sect2 (i=2, m1=64)
            R4C r = r4_cplx(make_float2(q[0][1], q[0][2]),
                            make_float2(q[1][1], q[1][2]),
                            make_float2(q[2][1], q[2][2]),
                            make_float2(q[3][1], q[3][2]),
                            s_tw[64], s_tw[128], s_tw[192]);
            out[1]  = r.o0.x; out[2]  = r.o0.y;
            out[13] = r.o3.x; out[14] = r.o3.y;
            out[9]  = r.o2.x; out[10] = r.o2.y;
            out[5]  = r.o1.x; out[6]  = r.o1.y;
        }
        {   // pass-2 sect3 (tail)
            float4 r = r4_tail(q[0][3], q[1][3], q[2][3], q[3][3]);
            out[3] = r.x; out[4] = r.y; out[11] = r.z; out[12] = r.w;
        }
        B[FDX(1, 16*k2 + 1)] = out[0];
#pragma unroll
        for (int j = 1; j <= 13; j += 2)
            *(float2*)&B[FDX(1, 16*k2 + j + 1)] = make_float2(out[j], out[j+1]);
        B[FDX(1, 16*k2 + 16)] = out[15];
    }
    __syncthreads();

    // ---- pass 3 : B(P1) -> A(P2), ido=16, l1=16 ----
    radf4_pass<1,2>(B, A, s_tw, 16, 16, 16, t);
    __syncthreads();

    // ---- fused pass 4+5 : A(P2) -> H (plain, shift 1) ----
#define RD1A(i) A[FDX(2, (i) + 1)]
#define RD2A(L) (*(const float2*)&A[FDX(2, (L) + 1)])
    if (t == 0) {
        // pass-4 sect1 (i=0) x4 -> pass-5 {sect1, i5=128, tail}
        float q0[4][4];
#pragma unroll
        for (int k4 = 0; k4 < 4; ++k4) {
            float4 r = r4_real(RD1A(64*k4), RD1A(64*(k4+4)),
                               RD1A(64*(k4+8)), RD1A(64*(k4+12)));
            q0[k4][0] = r.x; q0[k4][1] = r.y; q0[k4][2] = r.z; q0[k4][3] = r.w;
        }
        {   float4 s = r4_real(q0[0][0], q0[1][0], q0[2][0], q0[3][0]);
            H[1] = s.x; H[512] = s.y; H[513] = s.z; H[1024] = s.w; }
        {   R4C r = r4_cplx(make_float2(q0[0][1], q0[0][2]),
                            make_float2(q0[1][1], q0[1][2]),
                            make_float2(q0[2][1], q0[2][2]),
                            make_float2(q0[3][1], q0[3][2]),
                            s_tw[64], s_tw[128], s_tw[192]);
            *(float2*)&H[128] = r.o0; *(float2*)&H[896] = r.o3;
            *(float2*)&H[640] = r.o2; *(float2*)&H[384] = r.o1; }   // 512-128=384
        {   float4 s = r4_tail(q0[0][3], q0[1][3], q0[2][3], q0[3][3]);
            *(float2*)&H[256] = make_float2(s.x, s.y);
            *(float2*)&H[768] = make_float2(s.z, s.w); }
    } else if (t == 32) {
        // pass-4 tail x4 -> pass-5 {i5=64, i5=192}
        float qt[4][4];
#pragma unroll
        for (int k4 = 0; k4 < 4; ++k4) {
            float4 r = r4_tail(RD1A(63 + 64*k4), RD1A(63 + 64*(k4+4)),
                               RD1A(63 + 64*(k4+8)), RD1A(63 + 64*(k4+12)));
            qt[k4][0] = r.x; qt[k4][1] = r.y; qt[k4][2] = r.z; qt[k4][3] = r.w;
        }
        {   R4C r = r4_cplx(make_float2(qt[0][0], qt[0][1]),
                            make_float2(qt[1][0], qt[1][1]),
                            make_float2(qt[2][0], qt[2][1]),
                            make_float2(qt[3][0], qt[3][1]),
                            s_tw[32], s_tw[64], s_tw[96]);
            *(float2*)&H[64]  = r.o0; *(float2*)&H[960] = r.o3;
            *(float2*)&H[576] = r.o2; *(float2*)&H[448] = r.o1; }   // 512-64=448
        {   R4C r = r4_cplx(make_float2(qt[0][2], qt[0][3]),
                            make_float2(qt[1][2], qt[1][3]),
                            make_float2(qt[2][2], qt[2][3]),
                            make_float2(qt[3][2], qt[3][3]),
                            s_tw[96], s_tw[192], s_tw[288]);
            *(float2*)&H[192] = r.o0; *(float2*)&H[832] = r.o3;
            *(float2*)&H[704] = r.o2; *(float2*)&H[320] = r.o1; }   // 512-192=320
    } else if (t < 32) {
        // pass-4 sect2 (i4=2t) x4 -> pass-5 {i4, i4+128, 128-i4, 256-i4}
        const int i4 = 2 * t;
        float2 r0[4], r1[4], r2[4], r3[4];
        {
            float2 w1 = s_tw[4*t], w2 = s_tw[8*t], w3 = s_tw[12*t];
#pragma unroll
            for (int k4 = 0; k4 < 4; ++k4) {
                R4C r = r4_cplx(RD2A((i4-1) + 64*k4),
                                RD2A((i4-1) + 64*(k4+4)),
                                RD2A((i4-1) + 64*(k4+8)),
                                RD2A((i4-1) + 64*(k4+12)),
                                w1, w2, w3);
                r0[k4] = r.o0; r1[k4] = r.o1; r2[k4] = r.o2; r3[k4] = r.o3;
            }
        }
#define EMIT5(I5, V, W1, W2, W3) do { \
            R4C r = r4_cplx((V)[0], (V)[1], (V)[2], (V)[3], (W1), (W2), (W3)); \
            *(float2*)&H[(I5)]        = r.o0; \
            *(float2*)&H[1024 - (I5)] = r.o3; \
            *(float2*)&H[(I5) + 512]  = r.o2; \
            *(float2*)&H[512 - (I5)]  = r.o1; \
        } while (0)
        EMIT5(i4,        r0, s_tw[t],       s_tw[2*t],       s_tw[3*t]);
        EMIT5(i4 + 128,  r2, s_tw[64 + t],  s_tw[128 + 2*t], s_tw[192 + 3*t]);
        EMIT5(128 - i4,  r1, s_tw[64 - t],  s_tw[128 - 2*t], s_tw[192 - 3*t]);
        EMIT5(256 - i4,  r3, s_tw[128 - t], s_tw[256 - 2*t], s_tw[384 - 3*t]);
#undef EMIT5
    }
#undef RD1A
#undef RD2A
    __syncthreads();
    // H (shift 1): X0 = H[1]; Xk = (H[2k], H[2k+1]) k=1..511; X512 = H[1024]

    // ---- magnitudes (XLA EmitHypot) ----
    {
        const float2* h2 = (const float2*)H;
#pragma unroll
        for (int h = 0; h < 2; ++h) {
            int k = t + h * 256;
            float xrf, xif;
            if (k == 0) { xrf = H[1]; xif = 0.f; }
            else        { float2 v = h2[k]; xrf = v.x; xif = v.y; }
            s_mag[k] = xla_hypot(xrf, xif);
            s_sc[k]  = 0.f;
        }
        if (t == 0) {
            s_mag[512] = xla_hypot(H[1024], 0.f);
            s_sc[512]  = 0.f;
        }
        s_hist[t] = 0;
        s_goff[t] = 0;
    }
    __syncthreads();

    // ---- max mag (block reduce) ----
    float mv = fmaxf(s_mag[t], s_mag[t + 256]);
    if (t == 0) mv = fmaxf(mv, s_mag[512]);
#pragma unroll
    for (int o = 16; o; o >>= 1) mv = fmaxf(mv, __shfl_xor_sync(0xffffffffu, mv, o));
    if (lane == 0) s_wmax[wrp] = mv;
    __syncthreads();
    if (t == 0) {
        float m2 = s_wmax[0];
#pragma unroll
        for (int i2 = 1; i2 < 8; ++i2) m2 = fmaxf(m2, s_wmax[i2]);
        s_wmax[0] = m2 * 1.0000002f + 1e-30f;
    }
    __syncthreads();

    const float hi = s_wmax[0];
    const float inv = 256.f / hi;

    // ---- single-pass histogram ----
    for (int f = t; f < RR; f += TPB) {
        int b = min((int)(s_mag[f] * inv), 255);
        atomicAdd(&s_hist[b], 1);
    }
    __syncthreads();

    // ---- suffix scan ----
    {
        int v = s_hist[t];
#pragma unroll
        for (int d = 1; d < 32; d <<= 1) {
            int tmp = __shfl_down_sync(0xffffffffu, v, d);
            if (lane + d < 32) v += tmp;
        }
        if (lane == 0) s_wsumi[wrp] = v;
        __syncthreads();
        int add = 0;
#pragma unroll
        for (int w = 0; w < 8; ++w) add += (w > wrp) ? s_wsumi[w] : 0;
        v += add;
        s_hist[t] = v;
    }
    __syncthreads();

    // ---- cut bin ----
    {
        int sa = s_hist[t];
        int sb = (t == 255) ? 0 : s_hist[t + 1];
        if (sa >= kk && sb < kk) s_cut = t;
    }
    __syncthreads();
    const int cutb = s_cut;
    const int cnt = s_hist[cutb];

    // ---- compact candidates into per-bin segments ----
    for (int f = t; f < RR; f += TPB) {
        float m = s_mag[f];
        int b = min((int)(m * inv), 255);
        if (b >= cutb) {
            int gs = (b < 255) ? s_hist[b + 1] : 0;
            int off = atomicAdd(&s_goff[b], 1);
            s_ckey[gs + off] = (((unsigned long long)__float_as_uint(m)) << 10)
                             | (unsigned long long)(1023 - f);
        }
    }
    __syncthreads();

    // ---- exact rank within bin; scatter gains ----
    for (int i = t; i < cnt; i += TPB) {
        unsigned long long ki = s_ckey[i];
        float m = __uint_as_float((unsigned)(ki >> 10));
        int b = min((int)(m * inv), 255);
        int gs = (b < 255) ? s_hist[b + 1] : 0;
        int ge = gs + s_goff[b];
        int r  = gs;
        for (int j = gs; j < ge; ++j) r += (s_ckey[j] > ki) ? 1 : 0;
        if (r < kk) {
            int f = 1023 - (int)(ki & 1023ull);
            s_sc[f] = s_g[r];
        }
    }
    __syncthreads();

    // ---- pack scaled Hermitian spectrum for inverse ----
    float2* zb = (float2*)s_pool;
    {
        const float2* h2 = (const float2*)H;
        const float sc1 = 1.f / 1024.f;
#pragma unroll
        for (int h = 0; h < 2; ++h) {
            int k  = t + h * 256;
            int km = NN - k;
            float2 Yk, Ym;
            if (k == 0) Yk = make_float2(H[1], 0.f); else Yk = h2[k];
            if (km == 512) Ym = make_float2(H[1024], 0.f); else Ym = h2[km];
            float a1 = s_sc[k];  Yk.x *= a1; Yk.y *= a1;
            float a2 = s_sc[km]; Ym.x *= a2; Ym.y *= a2;
            float px = Yk.x + Ym.x, py = Yk.y - Ym.y;
            float qx = Yk.x - Ym.x, qy = Yk.y + Ym.y;
            float2 w = s_tw[k];
            float tx = qx * w.x + qy * w.y;
            float ty = qy * w.x - qx * w.y;
            zb[PIDX(__brev(k) >> 23)] = make_float2(sc1 * (px - ty), sc1 * (py + tx));
        }
    }
    __syncthreads();

    // ---- inverse 512-pt FFT: fused double radix-2 stages ----
#pragma unroll
    for (int lsp = 1; lsp <= 7; lsp += 2) {
        if (t < 128) {
            const int h1 = 1 << (lsp - 1);
            const int low = t & (h1 - 1);
            const int high = t >> (lsp - 1);
            const int bidx = low | (high << (lsp + 1));
            float2 z0 = zb[PIDX(bidx)];
            float2 z1 = zb[PIDX(bidx + h1)];
            float2 z2 = zb[PIDX(bidx + 2 * h1)];
            float2 z3 = zb[PIDX(bidx + 3 * h1)];
            float2 wa = s_tw[low << (10 - lsp)];
            int wbi = low << (9 - lsp);
            float2 wb = s_tw[wbi];
            float2 wc = s_tw[wbi + 256];
            float2 t1 = cmulc(z1, wa);
            float2 a0 = make_float2(z0.x + t1.x, z0.y + t1.y);
            float2 a1 = make_float2(z0.x - t1.x, z0.y - t1.y);
            float2 t2 = cmulc(z3, wa);
            float2 a2 = make_float2(z2.x + t2.x, z2.y + t2.y);
            float2 a3 = make_float2(z2.x - t2.x, z2.y - t2.y);
            float2 u = cmulc(a2, wb);
            float2 v = cmulc(a3, wc);
            zb[PIDX(bidx)]          = make_float2(a0.x + u.x, a0.y + u.y);
            zb[PIDX(bidx + h1)]     = make_float2(a1.x + v.x, a1.y + v.y);
            zb[PIDX(bidx + 2*h1)]   = make_float2(a0.x - u.x, a0.y - u.y);
            zb[PIDX(bidx + 3*h1)]   = make_float2(a1.x - v.x, a1.y - v.y);
        }
        __syncthreads();
    }

    // ---- final stage in registers, fused with bias add + gmem write ----
    {
        const float2* b2 = (const float2*)bias;
        float2* yr = (float2*)(y + row * DD);
        float2 u = zb[PIDX(t)];
        float2 v = zb[PIDX(t + 256)];
        float2 w = s_tw[t << 1];
        float2 vp = cmulc(v, w);
        float2 bb0 = b2[t];
        float2 bb1 = b2[t + 256];
        yr[t]       = make_float2(u.x + vp.x + bb0.x, u.y + vp.y + bb0.y);
        yr[t + 256] = make_float2(u.x - vp.x + bb1.x, u.y - vp.y + bb1.y);
    }
}

extern "C" void kernel_launch(void* const* d_in, const int* in_sizes, int n_in,
                              void* d_out, int out_size) {
    const float* x     = (const float*)d_in[0];
    const float* gains = (const float*)d_in[1];
    const float* bias  = (const float*)d_in[2];
    float* y = (float*)d_out;

    int rows = in_sizes[0] / DD;
    int kk = in_sizes[1];
    if (kk > KMAX) kk = KMAX;

    tw_init_kernel<<<3, 256>>>();
    spectral_kernel<<<rows, TPB>>>(x, gains, bias, y, kk);
}

// round 14
// speedup vs baseline: 2.1804x; 1.0555x over previous
#include <cuda_runtime.h>

#define DD 1024
#define NN 512
#define RR 513
#define TPB 256
#define KMAX 128
#define CKMAX 513

// padded index for inverse-FFT smem buffer (float2 units)
#define PIDX(i) ((i) + ((i) >> 4))
// per-life pads for forward scratch (float units; +2 steps keep float2 alignment)
#define FDX(P, i) ((P) == 1 ? (i) + 2 * ((i) >> 5) : \
                   (P) == 2 ? (i) + 2 * ((i) >> 6) : (i))

#define BSTRIDE 1092

// Twiddle table: g_tw[k] = (cos, -sin)(2*pi*k/1024), k=0..512, double-rounded to float.
__device__ float2 g_tw[RR];

__global__ void tw_init_kernel() {
    int i = blockIdx.x * blockDim.x + threadIdx.x;
    if (i < RR) {
        double a = (double)i / (double)NN;
        g_tw[i] = make_float2((float)cospi(a), (float)(-sinpi(a)));
    }
}

__device__ __forceinline__ float xla_hypot(float re, float im) {
    float a = fabsf(re), b = fabsf(im);
    float mx = fmaxf(a, b), mn = fminf(a, b);
    if (mx == 0.f) return 0.f;
    float div = __fdiv_rn(mn, mx);
    float t = __fadd_rn(1.f, __fmul_rn(div, div));
    return __fmul_rn(mx, __fsqrt_rn(t));
}

__device__ __forceinline__ float2 cmulc(float2 z, float2 w) {
    return make_float2(fmaf(z.x, w.x,  z.y * w.y),
                       fmaf(z.y, w.x, -z.x * w.y));
}

// ---- bit-exact radf4 butterfly helpers ----
__device__ __forceinline__ float4 r4_real(float c0, float c1, float c2, float c3) {
    float tr1 = c3 + c1, tr2 = c0 + c2;
    return make_float4(tr2 + tr1, c0 - c2, c3 - c1, tr2 - tr1);
}
__device__ __forceinline__ float4 r4_tail(float c0, float a, float cv, float b) {
    const float HS = 0.70710678118654752440f;
    float ti1 = __fmul_rn(-HS, __fadd_rn(a, b));
    float tr1 = __fmul_rn( HS, __fsub_rn(a, b));
    return make_float4(c0 + tr1, ti1 - cv, c0 - tr1, ti1 + cv);
}
struct R4C { float2 o0, o1, o2, o3; };
__device__ __forceinline__ R4C r4_cplx(float2 c0v, float2 cv1, float2 cv2, float2 cv3,
                                       float2 t1, float2 t2, float2 t3) {
    float w1r = t1.x, w1i = -t1.y;
    float w2r = t2.x, w2i = -t2.y;
    float w3r = t3.x, w3i = -t3.y;
    float cr2 = __fadd_rn(__fmul_rn(w1r, cv1.x), __fmul_rn(w1i, cv1.y));
    float ci2 = __fsub_rn(__fmul_rn(w1r, cv1.y), __fmul_rn(w1i, cv1.x));
    float cr3 = __fadd_rn(__fmul_rn(w2r, cv2.x), __fmul_rn(w2i, cv2.y));
    float ci3 = __fsub_rn(__fmul_rn(w2r, cv2.y), __fmul_rn(w2i, cv2.x));
    float cr4 = __fadd_rn(__fmul_rn(w3r, cv3.x), __fmul_rn(w3i, cv3.y));
    float ci4 = __fsub_rn(__fmul_rn(w3r, cv3.y), __fmul_rn(w3i, cv3.x));
    float tr1 = cr4 + cr2, tr4 = cr4 - cr2;
    float ti1 = ci2 + ci4, ti4 = ci2 - ci4;
    float tr2 = c0v.x + cr3, tr3 = c0v.x - cr3;
    float ti2 = c0v.y + ci3, ti3 = c0v.y - ci3;
    R4C r;
    r.o0 = make_float2(tr1 + tr2, ti1 + ti2);
    r.o3 = make_float2(tr2 - tr1, ti1 - ti2);
    r.o2 = make_float2(ti4 + tr3, tr4 + ti3);
    r.o1 = make_float2(tr3 - ti4, tr4 - ti3);
    return r;
}

// ---- generic radf4 middle pass (pass 3: B(P1) -> A(P2)) ----
template<int PIN, int POUT>
__device__ __forceinline__ void radf4_pass(
    const float* __restrict__ cc, float* __restrict__ ch,
    const float2* __restrict__ tw, int ido, int l1, int m_step, int t)
{
#define RD1(i)    cc[FDX(PIN, (i) + 1)]
#define RD2(L)    (*(const float2*)&cc[FDX(PIN, (L) + 1)])
#define WR1(i, v) do { ch[FDX(POUT, (i) + 1)] = (v); } while (0)
#define WR2(L, v) do { *(float2*)&ch[FDX(POUT, (L) + 1)] = (v); } while (0)
    if (t < l1) {
        int k = t;
        float4 r = r4_real(RD1(ido * k), RD1(ido * (k + l1)),
                           RD1(ido * (k + 2 * l1)), RD1(ido * (k + 3 * l1)));
        WR1(ido * (4 * k),               r.x);
        WR1((ido - 1) + ido * (1 + 4*k), r.y);
        WR1(ido * (2 + 4 * k),           r.z);
        WR1((ido - 1) + ido * (3 + 4*k), r.w);
    }
    const int nI = (ido >> 1) - 1;
    const int s2 = l1, e2 = l1 + l1 * nI;
    if (t >= s2 && t < e2) {
        int q = t - s2;
        int k = q % l1, ii = q / l1;
        int i = 2 + 2 * ii;
        int ic = ido - i;
        int m1 = (i >> 1) * m_step;
        R4C r = r4_cplx(RD2((i-1) + ido*k),
                        RD2((i-1) + ido*(k + l1)),
                        RD2((i-1) + ido*(k + 2*l1)),
                        RD2((i-1) + ido*(k + 3*l1)),
                        tw[m1], tw[2*m1], tw[3*m1]);
        WR2((i-1)  + ido*(4*k),     r.o0);
        WR2((ic-1) + ido*(3 + 4*k), r.o3);
        WR2((i-1)  + ido*(2 + 4*k), r.o2);
        WR2((ic-1) + ido*(1 + 4*k), r.o1);
    }
    if (t >= e2 && t < e2 + l1) {
        int k = t - e2;
        float4 r = r4_tail(RD1((ido-1) + ido*k), RD1((ido-1) + ido*(k + l1)),
                           RD1((ido-1) + ido*(k + 2*l1)), RD1((ido-1) + ido*(k + 3*l1)));
        WR1((ido-1) + ido*(4*k),     r.x);
        WR1(ido*(1 + 4*k),           r.y);
        WR1((ido-1) + ido*(2 + 4*k), r.z);
        WR1(ido*(3 + 4*k),           r.w);
    }
#undef RD1
#undef RD2
#undef WR1
#undef WR2
}

__global__ __launch_bounds__(TPB, 8) void spectral_kernel(
    const float* __restrict__ x, const float* __restrict__ gains,
    const float* __restrict__ bias, float* __restrict__ y, int kk)
{
    __shared__ __align__(16) float s_pool[3212];
    __shared__ float2 s_tw[RR];
    __shared__ float  s_sc[RR];
    __shared__ float  s_g[KMAX];
    __shared__ int    s_hist[256];
    __shared__ int    s_goff[256];
    __shared__ unsigned long long s_ckey[CKMAX];
    __shared__ int    s_wsumi[8];
    __shared__ float  s_wmax[8];
    __shared__ int    s_cut;

    float* B = s_pool;
    float* A = s_pool + BSTRIDE;
    float* H = s_pool + 2 * BSTRIDE;

    const int t = threadIdx.x;
    const int lane = t & 31;
    const int wrp = t >> 5;
    const long long row = blockIdx.x;
    const float* xrow = x + row * DD;

    // ---- fused pass 1+2 (threads 0..63) overlapped with s_tw/s_g staging ----
    if (t < 64) {
        const int k2 = t;
        float q[4][4];
#pragma unroll
        for (int m = 0; m < 4; ++m) {
            int base = k2 + 64 * m;
            float4 r = r4_real(xrow[base], xrow[base + 256],
                               xrow[base + 512], xrow[base + 768]);
            q[m][0] = r.x; q[m][1] = r.y; q[m][2] = r.z; q[m][3] = r.w;
        }
#define WB1(j, v) B[FDX(1, 16*k2 + (j) + 1)] = (v)
#define WB2(j, v) *(float2*)&B[FDX(1, 16*k2 + (j) + 1)] = (v)
        {   // pass-2 sect1 (i=0): out0, (out7,out8), out15
            float4 r = r4_real(q[0][0], q[1][0], q[2][0], q[3][0]);
            WB1(0, r.x); WB2(7, make_float2(r.y, r.z)); WB1(15, r.w);
        }
        {   // pass-2 sect3 (tail): (out3,out4), (out11,out12)
            float4 r = r4_tail(q[0][3], q[1][3], q[2][3], q[3][3]);
            WB2(3, make_float2(r.x, r.y)); WB2(11, make_float2(r.z, r.w));
        }
        {   // pass-2 sect2 (i=2, m1=64): (out1,2)=o0, (out5,6)=o1, (out9,10)=o2, (out13,14)=o3
            float2 w1 = g_tw[64], w2 = g_tw[128], w3 = g_tw[192];
            R4C r = r4_cplx(make_float2(q[0][1], q[0][2]),
                            make_float2(q[1][1], q[1][2]),
                            make_float2(q[2][1], q[2][2]),
                            make_float2(q[3][1], q[3][2]),
                            w1, w2, w3);
            WB2(1, r.o0); WB2(5, r.o1); WB2(9, r.o2); WB2(13, r.o3);
        }
#undef WB1
#undef WB2
    } else {
        for (int i = t - 64; i < RR; i += 192) s_tw[i] = g_tw[i];
        for (int i = t - 64; i < kk; i += 192) s_g[i] = gains[i];
    }
    __syncthreads();

    // ---- pass 3 : B(P1) -> A(P2), ido=16, l1=16 ----
    radf4_pass<1,2>(B, A, s_tw, 16, 16, 16, t);
    __syncthreads();

    // ---- fused pass 4+5 : A(P2) -> H; idle threads init selection arrays ----
#define RD1A(i) A[FDX(2, (i) + 1)]
#define RD2A(L) (*(const float2*)&A[FDX(2, (L) + 1)])
    if (t < 62) {
        // sect2 split: pair p = t/2 + 1 in [1,31], half h = t&1, i4 = 2p.
        const int p = (t >> 1) + 1;
        const int h = t & 1;
        const int i4 = 2 * p;
        float2 ra[4], rb[4];
        {
            float2 w1 = s_tw[4*p], w2 = s_tw[8*p], w3 = s_tw[12*p];
#pragma unroll
            for (int k4 = 0; k4 < 4; ++k4) {
                R4C r = r4_cplx(RD2A((i4-1) + 64*k4),
                                RD2A((i4-1) + 64*(k4+4)),
                                RD2A((i4-1) + 64*(k4+8)),
                                RD2A((i4-1) + 64*(k4+12)),
                                w1, w2, w3);
                ra[k4] = h ? r.o1 : r.o0;
                rb[k4] = h ? r.o3 : r.o2;
            }
        }
        const int I5a = h ? (128 - i4) : i4;
        const int I5b = h ? (256 - i4) : (i4 + 128);
        float2 wa1 = s_tw[h ? (64 - p)      : p];
        float2 wa2 = s_tw[h ? (128 - 2*p)   : 2*p];
        float2 wa3 = s_tw[h ? (192 - 3*p)   : 3*p];
        float2 wb1 = s_tw[h ? (128 - p)     : (64 + p)];
        float2 wb2 = s_tw[h ? (256 - 2*p)   : (128 + 2*p)];
        float2 wb3 = s_tw[h ? (384 - 3*p)   : (192 + 3*p)];
#define EMIT5(I5, V, W1, W2, W3) do { \
            R4C r = r4_cplx((V)[0], (V)[1], (V)[2], (V)[3], (W1), (W2), (W3)); \
            *(float2*)&H[(I5)]        = r.o0; \
            *(float2*)&H[1024 - (I5)] = r.o3; \
            *(float2*)&H[(I5) + 512]  = r.o2; \
            *(float2*)&H[512 - (I5)]  = r.o1; \
        } while (0)
        EMIT5(I5a, ra, wa1, wa2, wa3);
        EMIT5(I5b, rb, wb1, wb2, wb3);
#undef EMIT5
    } else if (t == 64) {
        // pass-4 sect1 (i=0) x4 -> pass-5 {sect1, i5=128, tail}
        float q0[4][4];
#pragma unroll
        for (int k4 = 0; k4 < 4; ++k4) {
            float4 r = r4_real(RD1A(64*k4), RD1A(64*(k4+4)),
                               RD1A(64*(k4+8)), RD1A(64*(k4+12)));
            q0[k4][0] = r.x; q0[k4][1] = r.y; q0[k4][2] = r.z; q0[k4][3] = r.w;
        }
        {   float4 s = r4_real(q0[0][0], q0[1][0], q0[2][0], q0[3][0]);
            H[1] = s.x; H[512] = s.y; H[513] = s.z; H[1024] = s.w; }
        {   R4C r = r4_cplx(make_float2(q0[0][1], q0[0][2]),
                            make_float2(q0[1][1], q0[1][2]),
                            make_float2(q0[2][1], q0[2][2]),
                            make_float2(q0[3][1], q0[3][2]),
                            s_tw[64], s_tw[128], s_tw[192]);
            *(float2*)&H[128] = r.o0; *(float2*)&H[896] = r.o3;
            *(float2*)&H[640] = r.o2; *(float2*)&H[384] = r.o1; }
        {   float4 s = r4_tail(q0[0][3], q0[1][3], q0[2][3], q0[3][3]);
            *(float2*)&H[256] = make_float2(s.x, s.y);
            *(float2*)&H[768] = make_float2(s.z, s.w); }
    } else if (t == 96) {
        // pass-4 tail x4 -> pass-5 {i5=64, i5=192}
        float qt[4][4];
#pragma unroll
        for (int k4 = 0; k4 < 4; ++k4) {
            float4 r = r4_tail(RD1A(63 + 64*k4), RD1A(63 + 64*(k4+4)),
                               RD1A(63 + 64*(k4+8)), RD1A(63 + 64*(k4+12)));
            qt[k4][0] = r.x; qt[k4][1] = r.y; qt[k4][2] = r.z; qt[k4][3] = r.w;
        }
        {   R4C r = r4_cplx(make_float2(qt[0][0], qt[0][1]),
                            make_float2(qt[1][0], qt[1][1]),
                            make_float2(qt[2][0], qt[2][1]),
                            make_float2(qt[3][0], qt[3][1]),
                            s_tw[32], s_tw[64], s_tw[96]);
            *(float2*)&H[64]  = r.o0; *(float2*)&H[960] = r.o3;
            *(float2*)&H[576] = r.o2; *(float2*)&H[448] = r.o1; }
        {   R4C r = r4_cplx(make_float2(qt[0][2], qt[0][3]),
                            make_float2(qt[1][2], qt[1][3]),
                            make_float2(qt[2][2], qt[2][3]),
                            make_float2(qt[3][2], qt[3][3]),
                            s_tw[96], s_tw[192], s_tw[288]);
            *(float2*)&H[192] = r.o0; *(float2*)&H[832] = r.o3;
            *(float2*)&H[704] = r.o2; *(float2*)&H[320] = r.o1; }
    } else if (t >= 128) {
        int u = t - 128;
        s_hist[u] = 0; s_goff[u] = 0;
        s_hist[u + 128] = 0; s_goff[u + 128] = 0;
        for (int i = u; i < RR; i += 128) s_sc[i] = 0.f;
    }
#undef RD1A
#undef RD2A
    __syncthreads();
    // H (shift 1): X0 = H[1]; Xk = (H[2k], H[2k+1]) k=1..511; X512 = H[1024]

    // ---- magnitudes in registers (XLA EmitHypot) + max reduce ----
    float m0, m1, m2 = 0.f;
    {
        const float2* h2 = (const float2*)H;
        float2 v0 = (t == 0) ? make_float2(H[1], 0.f) : h2[t];
        float2 v1 = h2[t + 256];
        m0 = xla_hypot(v0.x, v0.y);
        m1 = xla_hypot(v1.x, v1.y);
        if (t == 0) m2 = xla_hypot(H[1024], 0.f);
    }
    float mv = fmaxf(m0, m1);
    if (t == 0) mv = fmaxf(mv, m2);
#pragma unroll
    for (int o = 16; o; o >>= 1) mv = fmaxf(mv, __shfl_xor_sync(0xffffffffu, mv, o));
    if (lane == 0) s_wmax[wrp] = mv;
    __syncthreads();
    if (t == 0) {
        float mz = s_wmax[0];
#pragma unroll
        for (int i2 = 1; i2 < 8; ++i2) mz = fmaxf(mz, s_wmax[i2]);
        s_wmax[0] = mz * 1.0000002f + 1e-30f;
    }
    __syncthreads();

    const float hi = s_wmax[0];
    const float inv = 256.f / hi;
    const int b0 = min((int)(m0 * inv), 255);
    const int b1 = min((int)(m1 * inv), 255);
    int b2 = 0;

    // ---- histogram from registers ----
    atomicAdd(&s_hist[b0], 1);
    atomicAdd(&s_hist[b1], 1);
    if (t == 0) { b2 = min((int)(m2 * inv), 255); atomicAdd(&s_hist[b2], 1); }
    __syncthreads();

    // ---- suffix scan ----
    {
        int v = s_hist[t];
#pragma unroll
        for (int d = 1; d < 32; d <<= 1) {
            int tmp = __shfl_down_sync(0xffffffffu, v, d);
            if (lane + d < 32) v += tmp;
        }
        if (lane == 0) s_wsumi[wrp] = v;
        __syncthreads();
        int add = 0;
#pragma unroll
        for (int w = 0; w < 8; ++w) add += (w > wrp) ? s_wsumi[w] : 0;
        v += add;
        s_hist[t] = v;
    }
    __syncthreads();

    // ---- cut bin ----
    {
        int sa = s_hist[t];
        int sb = (t == 255) ? 0 : s_hist[t + 1];
        if (sa >= kk && sb < kk) s_cut = t;
    }
    __syncthreads();
    const int cutb = s_cut;
    const int cnt = s_hist[cutb];

    // ---- compact candidates from registers ----
    if (b0 >= cutb) {
        int gs = (b0 < 255) ? s_hist[b0 + 1] : 0;
        int off = atomicAdd(&s_goff[b0], 1);
        s_ckey[gs + off] = (((unsigned long long)__float_as_uint(m0)) << 10)
                         | (unsigned long long)(1023 - t);
    }
    if (b1 >= cutb) {
        int gs = (b1 < 255) ? s_hist[b1 + 1] : 0;
        int off = atomicAdd(&s_goff[b1], 1);
        s_ckey[gs + off] = (((unsigned long long)__float_as_uint(m1)) << 10)
                         | (unsigned long long)(1023 - (t + 256));
    }
    if (t == 0 && b2 >= cutb) {
        int gs = (b2 < 255) ? s_hist[b2 + 1] : 0;
        int off = atomicAdd(&s_goff[b2], 1);
        s_ckey[gs + off] = (((unsigned long long)__float_as_uint(m2)) << 10)
                         | (unsigned long long)(1023 - 512);
    }
    __syncthreads();

    // ---- exact rank within bin; scatter gains ----
    for (int i = t; i < cnt; i += TPB) {
        unsigned long long ki = s_ckey[i];
        float m = __uint_as_float((unsigned)(ki >> 10));
        int b = min((int)(m * inv), 255);
        int gs = (b < 255) ? s_hist[b + 1] : 0;
        int ge = gs + s_goff[b];
        int r  = gs;
        for (int j = gs; j < ge; ++j) r += (s_ckey[j] > ki) ? 1 : 0;
        if (r < kk) {
            int f = 1023 - (int)(ki & 1023ull);
            s_sc[f] = s_g[r];
        }
    }
    __syncthreads();

    // ---- pack scaled Hermitian spectrum for inverse ----
    float2* zb = (float2*)s_pool;
    {
        const float2* h2 = (const float2*)H;
        const float sc1 = 1.f / 1024.f;
#pragma unroll
        for (int h = 0; h < 2; ++h) {
            int k  = t + h * 256;
            int km = NN - k;
            float2 Yk, Ym;
            if (k == 0) Yk = make_float2(H[1], 0.f); else Yk = h2[k];
            if (km == 512) Ym = make_float2(H[1024], 0.f); else Ym = h2[km];
            float a1 = s_sc[k];  Yk.x *= a1; Yk.y *= a1;
            float a2 = s_sc[km]; Ym.x *= a2; Ym.y *= a2;
            float px = Yk.x + Ym.x, py = Yk.y - Ym.y;
            float qx = Yk.x - Ym.x, qy = Yk.y + Ym.y;
            float2 w = s_tw[k];
            float tx = qx * w.x + qy * w.y;
            float ty = qy * w.x - qx * w.y;
            zb[PIDX(__brev(k) >> 23)] = make_float2(sc1 * (px - ty), sc1 * (py + tx));
        }
    }
    __syncthreads();

    // ---- inverse 512-pt FFT: fused double radix-2 stages ----
#pragma unroll
    for (int lsp = 1; lsp <= 7; lsp += 2) {
        if (t < 128) {
            const int h1 = 1 << (lsp - 1);
            const int low = t & (h1 - 1);
            const int high = t >> (lsp - 1);
            const int bidx = low | (high << (lsp + 1));
            float2 z0 = zb[PIDX(bidx)];
            float2 z1 = zb[PIDX(bidx + h1)];
            float2 z2 = zb[PIDX(bidx + 2 * h1)];
            float2 z3 = zb[PIDX(bidx + 3 * h1)];
            float2 wa = s_tw[low << (10 - lsp)];
            int wbi = low << (9 - lsp);
            float2 wb = s_tw[wbi];
            float2 wc = s_tw[wbi + 256];
            float2 t1 = cmulc(z1, wa);
            float2 a0 = make_float2(z0.x + t1.x, z0.y + t1.y);
            float2 a1 = make_float2(z0.x - t1.x, z0.y - t1.y);
            float2 t2 = cmulc(z3, wa);
            float2 a2 = make_float2(z2.x + t2.x, z2.y + t2.y);
            float2 a3 = make_float2(z2.x - t2.x, z2.y - t2.y);
            float2 u = cmulc(a2, wb);
            float2 v = cmulc(a3, wc);
            zb[PIDX(bidx)]          = make_float2(a0.x + u.x, a0.y + u.y);
            zb[PIDX(bidx + h1)]     = make_float2(a1.x + v.x, a1.y + v.y);
            zb[PIDX(bidx + 2*h1)]   = make_float2(a0.x - u.x, a0.y - u.y);
            zb[PIDX(bidx + 3*h1)]   = make_float2(a1.x - v.x, a1.y - v.y);
        }
        __syncthreads();
    }

    // ---- final stage in registers, fused with bias add + gmem write ----
    {
        const float2* b2 = (const float2*)bias;
        float2* yr = (float2*)(y + row * DD);
        float2 u = zb[PIDX(t)];
        float2 v = zb[PIDX(t + 256)];
        float2 w = s_tw[t << 1];
        float2 vp = cmulc(v, w);
        float2 bb0 = b2[t];
        float2 bb1 = b2[t + 256];
        yr[t]       = make_float2(u.x + vp.x + bb0.x, u.y + vp.y + bb0.y);
        yr[t + 256] = make_float2(u.x - vp.x + bb1.x, u.y - vp.y + bb1.y);
    }
}

extern "C" void kernel_launch(void* const* d_in, const int* in_sizes, int n_in,
                              void* d_out, int out_size) {
    const float* x     = (const float*)d_in[0];
    const float* gains = (const float*)d_in[1];
    const float* bias  = (const float*)d_in[2];
    float* y = (float*)d_out;

    int rows = in_sizes[0] / DD;
    int kk = in_sizes[1];
    if (kk > KMAX) kk = KMAX;

    tw_init_kernel<<<3, 256>>>();
    spectral_kernel<<<rows, TPB>>>(x, gains, bias, y, kk);
}

// round 15
// speedup vs baseline: 2.3784x; 1.0908x over previous
#include <cuda_runtime.h>

#define DD 1024
#define NN 512
#define RR 513
#define TPB 256
#define KMAX 128
#define CKMAX 513

// padded index for inverse-FFT smem buffer (float2 units)
#define PIDX(i) ((i) + ((i) >> 4))
// per-life pads for forward scratch (float units; +2 steps keep float2 alignment)
#define FDX(P, i) ((P) == 1 ? (i) + 2 * ((i) >> 5) : \
                   (P) == 2 ? (i) + 2 * ((i) >> 6) : (i))

#define BSTRIDE 1092

// Twiddle table: g_tw[k] = (cos, -sin)(2*pi*k/1024), k=0..512, double-rounded to float.
__device__ float2 g_tw[RR];

__global__ void tw_init_kernel() {
    int i = blockIdx.x * blockDim.x + threadIdx.x;
    if (i < RR) {
        double a = (double)i / (double)NN;
        g_tw[i] = make_float2((float)cospi(a), (float)(-sinpi(a)));
    }
}

__device__ __forceinline__ float xla_hypot(float re, float im) {
    float a = fabsf(re), b = fabsf(im);
    float mx = fmaxf(a, b), mn = fminf(a, b);
    if (mx == 0.f) return 0.f;
    float div = __fdiv_rn(mn, mx);
    float t = __fadd_rn(1.f, __fmul_rn(div, div));
    return __fmul_rn(mx, __fsqrt_rn(t));
}

__device__ __forceinline__ float2 cmulc(float2 z, float2 w) {
    return make_float2(fmaf(z.x, w.x,  z.y * w.y),
                       fmaf(z.y, w.x, -z.x * w.y));
}

// ---- bit-exact radf4 butterfly helpers ----
__device__ __forceinline__ float4 r4_real(float c0, float c1, float c2, float c3) {
    float tr1 = c3 + c1, tr2 = c0 + c2;
    return make_float4(tr2 + tr1, c0 - c2, c3 - c1, tr2 - tr1);
}
__device__ __forceinline__ float4 r4_tail(float c0, float a, float cv, float b) {
    const float HS = 0.70710678118654752440f;
    float ti1 = __fmul_rn(-HS, __fadd_rn(a, b));
    float tr1 = __fmul_rn( HS, __fsub_rn(a, b));
    return make_float4(c0 + tr1, ti1 - cv, c0 - tr1, ti1 + cv);
}
struct R4C { float2 o0, o1, o2, o3; };
__device__ __forceinline__ R4C r4_cplx(float2 c0v, float2 cv1, float2 cv2, float2 cv3,
                                       float2 t1, float2 t2, float2 t3) {
    float w1r = t1.x, w1i = -t1.y;
    float w2r = t2.x, w2i = -t2.y;
    float w3r = t3.x, w3i = -t3.y;
    float cr2 = __fadd_rn(__fmul_rn(w1r, cv1.x), __fmul_rn(w1i, cv1.y));
    float ci2 = __fsub_rn(__fmul_rn(w1r, cv1.y), __fmul_rn(w1i, cv1.x));
    float cr3 = __fadd_rn(__fmul_rn(w2r, cv2.x), __fmul_rn(w2i, cv2.y));
    float ci3 = __fsub_rn(__fmul_rn(w2r, cv2.y), __fmul_rn(w2i, cv2.x));
    float cr4 = __fadd_rn(__fmul_rn(w3r, cv3.x), __fmul_rn(w3i, cv3.y));
    float ci4 = __fsub_rn(__fmul_rn(w3r, cv3.y), __fmul_rn(w3i, cv3.x));
    float tr1 = cr4 + cr2, tr4 = cr4 - cr2;
    float ti1 = ci2 + ci4, ti4 = ci2 - ci4;
    float tr2 = c0v.x + cr3, tr3 = c0v.x - cr3;
    float ti2 = c0v.y + ci3, ti3 = c0v.y - ci3;
    R4C r;
    r.o0 = make_float2(tr1 + tr2, ti1 + ti2);
    r.o3 = make_float2(tr2 - tr1, ti1 - ti2);
    r.o2 = make_float2(ti4 + tr3, tr4 + ti3);
    r.o1 = make_float2(tr3 - ti4, tr4 - ti3);
    return r;
}

// ---- generic radf4 middle pass (pass 3: B(P1) -> A(P2)) ----
template<int PIN, int POUT>
__device__ __forceinline__ void radf4_pass(
    const float* __restrict__ cc, float* __restrict__ ch,
    const float2* __restrict__ tw, int ido, int l1, int m_step, int t)
{
#define RD1(i)    cc[FDX(PIN, (i) + 1)]
#define RD2(L)    (*(const float2*)&cc[FDX(PIN, (L) + 1)])
#define WR1(i, v) do { ch[FDX(POUT, (i) + 1)] = (v); } while (0)
#define WR2(L, v) do { *(float2*)&ch[FDX(POUT, (L) + 1)] = (v); } while (0)
    if (t < l1) {
        int k = t;
        float4 r = r4_real(RD1(ido * k), RD1(ido * (k + l1)),
                           RD1(ido * (k + 2 * l1)), RD1(ido * (k + 3 * l1)));
        WR1(ido * (4 * k),               r.x);
        WR1((ido - 1) + ido * (1 + 4*k), r.y);
        WR1(ido * (2 + 4 * k),           r.z);
        WR1((ido - 1) + ido * (3 + 4*k), r.w);
    }
    const int nI = (ido >> 1) - 1;
    const int s2 = l1, e2 = l1 + l1 * nI;
    if (t >= s2 && t < e2) {
        int q = t - s2;
        int k = q % l1, ii = q / l1;
        int i = 2 + 2 * ii;
        int ic = ido - i;
        int m1 = (i >> 1) * m_step;
        R4C r = r4_cplx(RD2((i-1) + ido*k),
                        RD2((i-1) + ido*(k + l1)),
                        RD2((i-1) + ido*(k + 2*l1)),
                        RD2((i-1) + ido*(k + 3*l1)),
                        tw[m1], tw[2*m1], tw[3*m1]);
        WR2((i-1)  + ido*(4*k),     r.o0);
        WR2((ic-1) + ido*(3 + 4*k), r.o3);
        WR2((i-1)  + ido*(2 + 4*k), r.o2);
        WR2((ic-1) + ido*(1 + 4*k), r.o1);
    }
    if (t >= e2 && t < e2 + l1) {
        int k = t - e2;
        float4 r = r4_tail(RD1((ido-1) + ido*k), RD1((ido-1) + ido*(k + l1)),
                           RD1((ido-1) + ido*(k + 2*l1)), RD1((ido-1) + ido*(k + 3*l1)));
        WR1((ido-1) + ido*(4*k),     r.x);
        WR1(ido*(1 + 4*k),           r.y);
        WR1((ido-1) + ido*(2 + 4*k), r.z);
        WR1(ido*(3 + 4*k),           r.w);
    }
#undef RD1
#undef RD2
#undef WR1
#undef WR2
}

__global__ __launch_bounds__(TPB, 8) void spectral_kernel(
    const float* __restrict__ x, const float* __restrict__ gains,
    const float* __restrict__ bias, float* __restrict__ y, int kk)
{
    __shared__ __align__(16) float s_pool[3212];
    __shared__ float2 s_tw[RR];
    __shared__ float  s_sc[RR];
    __shared__ float  s_g[KMAX];
    __shared__ int    s_hist[256];
    __shared__ int    s_goff[256];
    __shared__ unsigned long long s_ckey[CKMAX];
    __shared__ int    s_wsumi[8];
    __shared__ float  s_wmax[8];
    __shared__ int    s_cut;

    float* B = s_pool;
    float* A = s_pool + BSTRIDE;
    float* H = s_pool + 2 * BSTRIDE;

    const int t = threadIdx.x;
    const int lane = t & 31;
    const int wrp = t >> 5;
    const long long row = blockIdx.x;
    const float* xrow = x + row * DD;

    // ---- fused pass 1+2 (threads 0..63) overlapped with s_tw/s_g staging ----
    if (t < 64) {
        const int k2 = t;
        float q[4][4];
#pragma unroll
        for (int m = 0; m < 4; ++m) {
            int base = k2 + 64 * m;
            float4 r = r4_real(xrow[base], xrow[base + 256],
                               xrow[base + 512], xrow[base + 768]);
            q[m][0] = r.x; q[m][1] = r.y; q[m][2] = r.z; q[m][3] = r.w;
        }
#define WB1(j, v) B[FDX(1, 16*k2 + (j) + 1)] = (v)
#define WB2(j, v) *(float2*)&B[FDX(1, 16*k2 + (j) + 1)] = (v)
        {   float4 r = r4_real(q[0][0], q[1][0], q[2][0], q[3][0]);
            WB1(0, r.x); WB2(7, make_float2(r.y, r.z)); WB1(15, r.w);
        }
        {   float4 r = r4_tail(q[0][3], q[1][3], q[2][3], q[3][3]);
            WB2(3, make_float2(r.x, r.y)); WB2(11, make_float2(r.z, r.w));
        }
        {   float2 w1 = g_tw[64], w2 = g_tw[128], w3 = g_tw[192];
            R4C r = r4_cplx(make_float2(q[0][1], q[0][2]),
                            make_float2(q[1][1], q[1][2]),
                            make_float2(q[2][1], q[2][2]),
                            make_float2(q[3][1], q[3][2]),
                            w1, w2, w3);
            WB2(1, r.o0); WB2(5, r.o1); WB2(9, r.o2); WB2(13, r.o3);
        }
#undef WB1
#undef WB2
    } else {
        for (int i = t - 64; i < RR; i += 192) s_tw[i] = g_tw[i];
        for (int i = t - 64; i < kk; i += 192) s_g[i] = gains[i];
    }
    __syncthreads();

    // ---- pass 3 : B(P1) -> A(P2), ido=16, l1=16 ----
    radf4_pass<1,2>(B, A, s_tw, 16, 16, 16, t);
    __syncthreads();

    // ---- fused pass 4+5 : A(P2) -> H; idle threads init selection arrays ----
#define RD1A(i) A[FDX(2, (i) + 1)]
#define RD2A(L) (*(const float2*)&A[FDX(2, (L) + 1)])
    if (t < 62) {
        const int p = (t >> 1) + 1;
        const int h = t & 1;
        const int i4 = 2 * p;
        float2 ra[4], rb[4];
        {
            float2 w1 = s_tw[4*p], w2 = s_tw[8*p], w3 = s_tw[12*p];
#pragma unroll
            for (int k4 = 0; k4 < 4; ++k4) {
                R4C r = r4_cplx(RD2A((i4-1) + 64*k4),
                                RD2A((i4-1) + 64*(k4+4)),
                                RD2A((i4-1) + 64*(k4+8)),
                                RD2A((i4-1) + 64*(k4+12)),
                                w1, w2, w3);
                ra[k4] = h ? r.o1 : r.o0;
                rb[k4] = h ? r.o3 : r.o2;
            }
        }
        const int I5a = h ? (128 - i4) : i4;
        const int I5b = h ? (256 - i4) : (i4 + 128);
        float2 wa1 = s_tw[h ? (64 - p)      : p];
        float2 wa2 = s_tw[h ? (128 - 2*p)   : 2*p];
        float2 wa3 = s_tw[h ? (192 - 3*p)   : 3*p];
        float2 wb1 = s_tw[h ? (128 - p)     : (64 + p)];
        float2 wb2 = s_tw[h ? (256 - 2*p)   : (128 + 2*p)];
        float2 wb3 = s_tw[h ? (384 - 3*p)   : (192 + 3*p)];
#define EMIT5(I5, V, W1, W2, W3) do { \
            R4C r = r4_cplx((V)[0], (V)[1], (V)[2], (V)[3], (W1), (W2), (W3)); \
            *(float2*)&H[(I5)]        = r.o0; \
            *(float2*)&H[1024 - (I5)] = r.o3; \
            *(float2*)&H[(I5) + 512]  = r.o2; \
            *(float2*)&H[512 - (I5)]  = r.o1; \
        } while (0)
        EMIT5(I5a, ra, wa1, wa2, wa3);
        EMIT5(I5b, rb, wb1, wb2, wb3);
#undef EMIT5
    } else if (t == 64) {
        float q0[4][4];
#pragma unroll
        for (int k4 = 0; k4 < 4; ++k4) {
            float4 r = r4_real(RD1A(64*k4), RD1A(64*(k4+4)),
                               RD1A(64*(k4+8)), RD1A(64*(k4+12)));
            q0[k4][0] = r.x; q0[k4][1] = r.y; q0[k4][2] = r.z; q0[k4][3] = r.w;
        }
        {   float4 s = r4_real(q0[0][0], q0[1][0], q0[2][0], q0[3][0]);
            H[1] = s.x; H[512] = s.y; H[513] = s.z; H[1024] = s.w; }
        {   R4C r = r4_cplx(make_float2(q0[0][1], q0[0][2]),
                            make_float2(q0[1][1], q0[1][2]),
                            make_float2(q0[2][1], q0[2][2]),
                            make_float2(q0[3][1], q0[3][2]),
                            s_tw[64], s_tw[128], s_tw[192]);
            *(float2*)&H[128] = r.o0; *(float2*)&H[896] = r.o3;
            *(float2*)&H[640] = r.o2; *(float2*)&H[384] = r.o1; }
        {   float4 s = r4_tail(q0[0][3], q0[1][3], q0[2][3], q0[3][3]);
            *(float2*)&H[256] = make_float2(s.x, s.y);
            *(float2*)&H[768] = make_float2(s.z, s.w); }
    } else if (t == 96) {
        float qt[4][4];
#pragma unroll
        for (int k4 = 0; k4 < 4; ++k4) {
            float4 r = r4_tail(RD1A(63 + 64*k4), RD1A(63 + 64*(k4+4)),
                               RD1A(63 + 64*(k4+8)), RD1A(63 + 64*(k4+12)));
            qt[k4][0] = r.x; qt[k4][1] = r.y; qt[k4][2] = r.z; qt[k4][3] = r.w;
        }
        {   R4C r = r4_cplx(make_float2(qt[0][0], qt[0][1]),
                            make_float2(qt[1][0], qt[1][1]),
                            make_float2(qt[2][0], qt[2][1]),
                            make_float2(qt[3][0], qt[3][1]),
                            s_tw[32], s_tw[64], s_tw[96]);
            *(float2*)&H[64]  = r.o0; *(float2*)&H[960] = r.o3;
            *(float2*)&H[576] = r.o2; *(float2*)&H[448] = r.o1; }
        {   R4C r = r4_cplx(make_float2(qt[0][2], qt[0][3]),
                            make_float2(qt[1][2], qt[1][3]),
                            make_float2(qt[2][2], qt[2][3]),
                            make_float2(qt[3][2], qt[3][3]),
                            s_tw[96], s_tw[192], s_tw[288]);
            *(float2*)&H[192] = r.o0; *(float2*)&H[832] = r.o3;
            *(float2*)&H[704] = r.o2; *(float2*)&H[320] = r.o1; }
    } else if (t >= 128) {
        int u = t - 128;
        s_hist[u] = 0; s_goff[u] = 0;
        s_hist[u + 128] = 0; s_goff[u + 128] = 0;
        for (int i = u; i < RR; i += 128) s_sc[i] = 0.f;
    }
#undef RD1A
#undef RD2A
    __syncthreads();
    // H (shift 1): X0 = H[1]; Xk = (H[2k], H[2k+1]) k=1..511; X512 = H[1024]

    // ---- magnitudes in registers (XLA EmitHypot) + max reduce ----
    float m0, m1, m2 = 0.f;
    {
        const float2* h2 = (const float2*)H;
        float2 v0 = (t == 0) ? make_float2(H[1], 0.f) : h2[t];
        float2 v1 = h2[t + 256];
        m0 = xla_hypot(v0.x, v0.y);
        m1 = xla_hypot(v1.x, v1.y);
        if (t == 0) m2 = xla_hypot(H[1024], 0.f);
    }
    float mv = fmaxf(m0, m1);
    if (t == 0) mv = fmaxf(mv, m2);
#pragma unroll
    for (int o = 16; o; o >>= 1) mv = fmaxf(mv, __shfl_xor_sync(0xffffffffu, mv, o));
    if (lane == 0) s_wmax[wrp] = mv;
    __syncthreads();
    if (t == 0) {
        float mz = s_wmax[0];
#pragma unroll
        for (int i2 = 1; i2 < 8; ++i2) mz = fmaxf(mz, s_wmax[i2]);
        s_wmax[0] = mz * 1.0000002f + 1e-30f;
    }
    __syncthreads();

    const float hi = s_wmax[0];
    const float inv = 256.f / hi;
    const int b0 = min((int)(m0 * inv), 255);
    const int b1 = min((int)(m1 * inv), 255);
    int b2 = 0;

    // ---- histogram from registers ----
    atomicAdd(&s_hist[b0], 1);
    atomicAdd(&s_hist[b1], 1);
    if (t == 0) { b2 = min((int)(m2 * inv), 255); atomicAdd(&s_hist[b2], 1); }
    __syncthreads();

    // ---- suffix scan ----
    {
        int v = s_hist[t];
#pragma unroll
        for (int d = 1; d < 32; d <<= 1) {
            int tmp = __shfl_down_sync(0xffffffffu, v, d);
            if (lane + d < 32) v += tmp;
        }
        if (lane == 0) s_wsumi[wrp] = v;
        __syncthreads();
        int add = 0;
#pragma unroll
        for (int w = 0; w < 8; ++w) add += (w > wrp) ? s_wsumi[w] : 0;
        v += add;
        s_hist[t] = v;
    }
    __syncthreads();

    // ---- cut bin ----
    {
        int sa = s_hist[t];
        int sb = (t == 255) ? 0 : s_hist[t + 1];
        if (sa >= kk && sb < kk) s_cut = t;
    }
    __syncthreads();
    const int cutb = s_cut;
    const int cnt = s_hist[cutb];

    // ---- compact candidates from registers ----
    if (b0 >= cutb) {
        int gs = (b0 < 255) ? s_hist[b0 + 1] : 0;
        int off = atomicAdd(&s_goff[b0], 1);
        s_ckey[gs + off] = (((unsigned long long)__float_as_uint(m0)) << 10)
                         | (unsigned long long)(1023 - t);
    }
    if (b1 >= cutb) {
        int gs = (b1 < 255) ? s_hist[b1 + 1] : 0;
        int off = atomicAdd(&s_goff[b1], 1);
        s_ckey[gs + off] = (((unsigned long long)__float_as_uint(m1)) << 10)
                         | (unsigned long long)(1023 - (t + 256));
    }
    if (t == 0 && b2 >= cutb) {
        int gs = (b2 < 255) ? s_hist[b2 + 1] : 0;
        int off = atomicAdd(&s_goff[b2], 1);
        s_ckey[gs + off] = (((unsigned long long)__float_as_uint(m2)) << 10)
                         | (unsigned long long)(1023 - 512);
    }
    __syncthreads();

    // ---- exact rank within bin; scatter gains ----
    for (int i = t; i < cnt; i += TPB) {
        unsigned long long ki = s_ckey[i];
        float m = __uint_as_float((unsigned)(ki >> 10));
        int b = min((int)(m * inv), 255);
        int gs = (b < 255) ? s_hist[b + 1] : 0;
        int ge = gs + s_goff[b];
        int r  = gs;
        for (int j = gs; j < ge; ++j) r += (s_ckey[j] > ki) ? 1 : 0;
        if (r < kk) {
            int f = 1023 - (int)(ki & 1023ull);
            s_sc[f] = s_g[r];
        }
    }
    __syncthreads();

    // ---- pack scaled Hermitian spectrum + FUSED inverse stage 1 ----
    // thread t computes z(k=t) and z(k=t+256); their bitrev slots are br, br+1
    // and stage 1 (twiddle 1) combines exactly those -> write sum/diff directly.
    float2* zb = (float2*)s_pool;
    {
        const float2* h2 = (const float2*)H;
        const float sc1 = 1.f / 1024.f;
        float2 st[2];
#pragma unroll
        for (int h = 0; h < 2; ++h) {
            int k  = t + h * 256;
            int km = NN - k;
            float2 Yk, Ym;
            if (k == 0) Yk = make_float2(H[1], 0.f); else Yk = h2[k];
            if (km == 512) Ym = make_float2(H[1024], 0.f); else Ym = h2[km];
            float a1 = s_sc[k];  Yk.x *= a1; Yk.y *= a1;
            float a2 = s_sc[km]; Ym.x *= a2; Ym.y *= a2;
            float px = Yk.x + Ym.x, py = Yk.y - Ym.y;
            float qx = Yk.x - Ym.x, qy = Yk.y + Ym.y;
            float2 w = s_tw[k];
            float tx = qx * w.x + qy * w.y;
            float ty = qy * w.x - qx * w.y;
            st[h] = make_float2(sc1 * (px - ty), sc1 * (py + tx));
        }
        int br = __brev(t) >> 23;   // 9-bit reversal; even for t<256
        zb[PIDX(br)]     = make_float2(st[0].x + st[1].x, st[0].y + st[1].y);
        zb[PIDX(br + 1)] = make_float2(st[0].x - st[1].x, st[0].y - st[1].y);
    }
    __syncthreads();

    // ---- inverse: fused double radix-2 stages (2,3)(4,5)(6,7) ----
#pragma unroll
    for (int lsp = 2; lsp <= 6; lsp += 2) {
        if (t < 128) {
            const int h1 = 1 << (lsp - 1);
            const int low = t & (h1 - 1);
            const int high = t >> (lsp - 1);
            const int bidx = low | (high << (lsp + 1));
            float2 z0 = zb[PIDX(bidx)];
            float2 z1 = zb[PIDX(bidx + h1)];
            float2 z2 = zb[PIDX(bidx + 2 * h1)];
            float2 z3 = zb[PIDX(bidx + 3 * h1)];
            float2 wa = s_tw[low << (10 - lsp)];
            int wbi = low << (9 - lsp);
            float2 wb = s_tw[wbi];
            float2 wc = s_tw[wbi + 256];
            float2 t1 = cmulc(z1, wa);
            float2 a0 = make_float2(z0.x + t1.x, z0.y + t1.y);
            float2 a1 = make_float2(z0.x - t1.x, z0.y - t1.y);
            float2 t2 = cmulc(z3, wa);
            float2 a2 = make_float2(z2.x + t2.x, z2.y + t2.y);
            float2 a3 = make_float2(z2.x - t2.x, z2.y - t2.y);
            float2 u = cmulc(a2, wb);
            float2 v = cmulc(a3, wc);
            zb[PIDX(bidx)]          = make_float2(a0.x + u.x, a0.y + u.y);
            zb[PIDX(bidx + h1)]     = make_float2(a1.x + v.x, a1.y + v.y);
            zb[PIDX(bidx + 2*h1)]   = make_float2(a0.x - u.x, a0.y - u.y);
            zb[PIDX(bidx + 3*h1)]   = make_float2(a1.x - v.x, a1.y - v.y);
        }
        __syncthreads();
    }

    // ---- fused stages 8+9 + bias add + gmem write (threads 0..127, 4 outputs) ----
    if (t < 128) {
        const float2* b2 = (const float2*)bias;
        float2* yr = (float2*)(y + row * DD);
        float2 u0 = zb[PIDX(t)];
        float2 u1 = zb[PIDX(t + 128)];
        float2 u2 = zb[PIDX(t + 256)];
        float2 u3 = zb[PIDX(t + 384)];
        float2 w8 = s_tw[t << 2];
        float2 t1 = cmulc(u1, w8);
        float2 a0 = make_float2(u0.x + t1.x, u0.y + t1.y);
        float2 a1 = make_float2(u0.x - t1.x, u0.y - t1.y);
        float2 t2 = cmulc(u3, w8);
        float2 a2 = make_float2(u2.x + t2.x, u2.y + t2.y);
        float2 a3 = make_float2(u2.x - t2.x, u2.y - t2.y);
        float2 w9a = s_tw[t << 1];
        float2 w9b = s_tw[(t << 1) + 256];
        float2 v0 = cmulc(a2, w9a);
        float2 v1 = cmulc(a3, w9b);
        float2 bb0 = b2[t];
        float2 bb1 = b2[t + 128];
        float2 bb2 = b2[t + 256];
        float2 bb3 = b2[t + 384];
        yr[t]       = make_float2(a0.x + v0.x + bb0.x, a0.y + v0.y + bb0.y);
        yr[t + 128] = make_float2(a1.x + v1.x + bb1.x, a1.y + v1.y + bb1.y);
        yr[t + 256] = make_float2(a0.x - v0.x + bb2.x, a0.y - v0.y + bb2.y);
        yr[t + 384] = make_float2(a1.x - v1.x + bb3.x, a1.y - v1.y + bb3.y);
    }
}

extern "C" void kernel_launch(void* const* d_in, const int* in_sizes, int n_in,
                              void* d_out, int out_size) {
    const float* x     = (const float*)d_in[0];
    const float* gains = (const float*)d_in[1];
    const float* bias  = (const float*)d_in[2];
    float* y = (float*)d_out;

    int rows = in_sizes[0] / DD;
    int kk = in_sizes[1];
    if (kk > KMAX) kk = KMAX;

    tw_init_kernel<<<3, 256>>>();
    spectral_kernel<<<rows, TPB>>>(x, gains, bias, y, kk);
}